// round 2
// baseline (speedup 1.0000x reference)
#include <cuda_runtime.h>
#include <math.h>

// ---------------- problem constants ----------------
#define NB   8
#define HH   36
#define WW   100
#define HW   3600      // 36*100
#define C0   512
#define C1   1024
#define C2   128
#define NCLS 5
#define NPIX 28800     // NB*HW
#define K1   4608      // 512*9
#define SEG_ELEMS 9216000  // 8*5*288*800

// ---------------- scratch (device globals; no allocation allowed) ----------------
__device__ __align__(16) float g_h1[NB * C1 * HW];     // conv1 output (8,1024,36,100)
__device__ __align__(16) float g_h2[NB * C2 * HW];     // conv2 / message-pass state (8,128,36,100)
__device__ __align__(16) float g_score[NB * NCLS * HW];// head conv output (8,5,36,100)
__device__ __align__(16) float g_pool[NB * 4500];      // softmax+pool features
__device__ __align__(16) float g_f1[NB * 128];         // fc1 output

// =====================================================================
// conv1: dilated 3x3 (dil=4, pad=4), 512->1024, + BN1 + ReLU
// GEMM: M=1024 (co), N=28800 (pixels), K=4608 (ci*9). 128x128x8 tiles.
// =====================================================================
__global__ __launch_bounds__(256)
void conv1_kernel(const float* __restrict__ x, const float* __restrict__ w,
                  const float* __restrict__ bg, const float* __restrict__ bb,
                  const float* __restrict__ bm, const float* __restrict__ bv)
{
    __shared__ float As[8][128];
    __shared__ float Bs[8][128];
    const int n0 = blockIdx.x * 128;
    const int m0 = blockIdx.y * 128;
    const int t  = threadIdx.x;
    const int tx = t & 15, ty = t >> 4;

    // B-load mapping: 8 k-rows x 128 n-cols, each thread one float4 of n
    const int bk  = t >> 5;
    const int bn4 = (t & 31) << 2;
    int pb[4], poh[4], pow_[4];
#pragma unroll
    for (int i = 0; i < 4; i++) {
        int n = n0 + bn4 + i;
        pb[i] = n / HW;
        int r = n - pb[i] * HW;
        poh[i] = r / WW;
        pow_[i] = r - poh[i] * WW;
    }
    // A-load mapping
    const int aRow = t >> 1;
    const int aCol = (t & 1) << 2;
    const float* aPtr = w + (size_t)(m0 + aRow) * K1 + aCol;

    float acc[8][8];
#pragma unroll
    for (int i = 0; i < 8; i++)
#pragma unroll
        for (int j = 0; j < 8; j++) acc[i][j] = 0.f;

    for (int k0 = 0; k0 < K1; k0 += 8) {
        float4 av = *(const float4*)(aPtr + k0);
        As[aCol + 0][aRow] = av.x;
        As[aCol + 1][aRow] = av.y;
        As[aCol + 2][aRow] = av.z;
        As[aCol + 3][aRow] = av.w;

        int k  = k0 + bk;
        int ci = k / 9;
        int kk = k - ci * 9;
        int kh = kk / 3;
        int kw = kk - kh * 3;
        int dh = kh * 4 - 4, dw = kw * 4 - 4;
        float tv[4];
#pragma unroll
        for (int i = 0; i < 4; i++) {
            int ih = poh[i] + dh, iw = pow_[i] + dw;
            float v = 0.f;
            if ((unsigned)ih < (unsigned)HH && (unsigned)iw < (unsigned)WW)
                v = __ldg(x + ((size_t)(pb[i] * C0 + ci) * HH + ih) * WW + iw);
            tv[i] = v;
        }
        *(float4*)&Bs[bk][bn4] = make_float4(tv[0], tv[1], tv[2], tv[3]);
        __syncthreads();

#pragma unroll
        for (int kk2 = 0; kk2 < 8; kk2++) {
            float ar[8], br[8];
#pragma unroll
            for (int i = 0; i < 8; i++) ar[i] = As[kk2][ty * 8 + i];
#pragma unroll
            for (int j = 0; j < 8; j++) br[j] = Bs[kk2][tx * 8 + j];
#pragma unroll
            for (int i = 0; i < 8; i++)
#pragma unroll
                for (int j = 0; j < 8; j++) acc[i][j] += ar[i] * br[j];
        }
        __syncthreads();
    }

#pragma unroll
    for (int i = 0; i < 8; i++) {
        int co = m0 + ty * 8 + i;
        float s    = bg[co] / sqrtf(bv[co] + 1e-5f);
        float bias = bb[co] - bm[co] * s;
#pragma unroll
        for (int j = 0; j < 8; j++) {
            int n  = n0 + tx * 8 + j;
            int b_ = n / HW;
            int r  = n - b_ * HW;
            float v = acc[i][j] * s + bias;
            g_h1[(size_t)(b_ * C1 + co) * HW + r] = fmaxf(v, 0.f);
        }
    }
}

// =====================================================================
// conv2: 1x1, 1024->128, + BN2 + ReLU. GEMM M=128, N=28800, K=1024.
// =====================================================================
__global__ __launch_bounds__(256)
void conv2_kernel(const float* __restrict__ w,
                  const float* __restrict__ bg, const float* __restrict__ bb,
                  const float* __restrict__ bm, const float* __restrict__ bv)
{
    __shared__ float As[8][128];
    __shared__ float Bs[8][128];
    const int n0 = blockIdx.x * 128;
    const int t  = threadIdx.x;
    const int tx = t & 15, ty = t >> 4;

    const int bk  = t >> 5;
    const int bn4 = (t & 31) << 2;
    int pb[4], pr[4];
#pragma unroll
    for (int i = 0; i < 4; i++) {
        int n = n0 + bn4 + i;
        pb[i] = n / HW;
        pr[i] = n - pb[i] * HW;
    }
    const int aRow = t >> 1;
    const int aCol = (t & 1) << 2;
    const float* aPtr = w + (size_t)aRow * C1 + aCol;

    float acc[8][8];
#pragma unroll
    for (int i = 0; i < 8; i++)
#pragma unroll
        for (int j = 0; j < 8; j++) acc[i][j] = 0.f;

    for (int k0 = 0; k0 < C1; k0 += 8) {
        float4 av = *(const float4*)(aPtr + k0);
        As[aCol + 0][aRow] = av.x;
        As[aCol + 1][aRow] = av.y;
        As[aCol + 2][aRow] = av.z;
        As[aCol + 3][aRow] = av.w;

        int k = k0 + bk;
        float tv[4];
#pragma unroll
        for (int i = 0; i < 4; i++)
            tv[i] = g_h1[(size_t)(pb[i] * C1 + k) * HW + pr[i]];
        *(float4*)&Bs[bk][bn4] = make_float4(tv[0], tv[1], tv[2], tv[3]);
        __syncthreads();

#pragma unroll
        for (int kk2 = 0; kk2 < 8; kk2++) {
            float ar[8], br[8];
#pragma unroll
            for (int i = 0; i < 8; i++) ar[i] = As[kk2][ty * 8 + i];
#pragma unroll
            for (int j = 0; j < 8; j++) br[j] = Bs[kk2][tx * 8 + j];
#pragma unroll
            for (int i = 0; i < 8; i++)
#pragma unroll
                for (int j = 0; j < 8; j++) acc[i][j] += ar[i] * br[j];
        }
        __syncthreads();
    }

#pragma unroll
    for (int i = 0; i < 8; i++) {
        int co = ty * 8 + i;
        float s    = bg[co] / sqrtf(bv[co] + 1e-5f);
        float bias = bb[co] - bm[co] * s;
#pragma unroll
        for (int j = 0; j < 8; j++) {
            int n  = n0 + tx * 8 + j;
            int b_ = n / HW;
            int r  = n - b_ * HW;
            float v = acc[i][j] * s + bias;
            g_h2[(size_t)(b_ * C2 + co) * HW + r] = fmaxf(v, 0.f);
        }
    }
}

// =====================================================================
// message-pass step: cur += relu(conv1d(prev, w)), conv along axis of
// length L (pad 4, k=9), 128ch -> 128ch.
// Element address in (b,ci) plane: off + p*posStride.
// Grid: (8 batches, 16 co-groups of 8). In-place on g_h2.
// =====================================================================
template <int L, int THREADS>
__global__ __launch_bounds__(THREADS)
void msg_step_kernel(const float* __restrict__ wgt, int prevOff, int curOff, int posStride)
{
    constexpr int CO_BLK = 8;
    constexpr int LP = L + 8;
    extern __shared__ float sm[];
    float* prev = sm;                 // 128 * LP, zero-padded 4 each side
    float* ws   = sm + 128 * LP;      // CO_BLK * 128 * 9

    const int b   = blockIdx.x;
    const int cog = blockIdx.y * CO_BLK;
    const int tid = threadIdx.x;

    for (int i = tid; i < 128 * LP; i += THREADS) {
        int ci = i / LP;
        int p  = i - ci * LP - 4;
        prev[i] = ((unsigned)p < (unsigned)L)
                    ? g_h2[(size_t)(b * C2 + ci) * HW + prevOff + p * posStride]
                    : 0.f;
    }
    for (int i = tid; i < CO_BLK * 128 * 9; i += THREADS)
        ws[i] = wgt[(size_t)cog * 128 * 9 + i];
    __syncthreads();

    constexpr int NT = CO_BLK * (L / 4);
    if (tid < NT) {
        const int co = tid / (L / 4);
        const int p0 = (tid - co * (L / 4)) * 4;
        float acc0 = 0.f, acc1 = 0.f, acc2 = 0.f, acc3 = 0.f;
        const float* wbase = ws + co * 128 * 9;
        for (int ci = 0; ci < 128; ci++) {
            const float4* pr4 = (const float4*)(prev + ci * LP + p0);
            float4 a0 = pr4[0], a1 = pr4[1], a2 = pr4[2];
            float xv[12] = {a0.x, a0.y, a0.z, a0.w,
                            a1.x, a1.y, a1.z, a1.w,
                            a2.x, a2.y, a2.z, a2.w};
            const float* wp = wbase + ci * 9;
#pragma unroll
            for (int k = 0; k < 9; k++) {
                float wk = wp[k];
                acc0 += xv[k]     * wk;
                acc1 += xv[k + 1] * wk;
                acc2 += xv[k + 2] * wk;
                acc3 += xv[k + 3] * wk;
            }
        }
        const size_t base = (size_t)(b * C2 + cog + co) * HW + curOff;
        g_h2[base + (size_t)(p0 + 0) * posStride] += fmaxf(acc0, 0.f);
        g_h2[base + (size_t)(p0 + 1) * posStride] += fmaxf(acc1, 0.f);
        g_h2[base + (size_t)(p0 + 2) * posStride] += fmaxf(acc2, 0.f);
        g_h2[base + (size_t)(p0 + 3) * posStride] += fmaxf(acc3, 0.f);
    }
}

#define MSG_SMEM_100 ((128 * 108 + 8 * 128 * 9) * 4)
#define MSG_SMEM_36  ((128 * 44  + 8 * 128 * 9) * 4)

// =====================================================================
// head: 1x1 conv 128->5 + bias
// =====================================================================
__global__ void head_kernel(const float* __restrict__ w2, const float* __restrict__ b2)
{
    int n = blockIdx.x * blockDim.x + threadIdx.x;
    if (n >= NPIX) return;
    int b = n / HW;
    int r = n - b * HW;
    float s[NCLS];
#pragma unroll
    for (int c = 0; c < NCLS; c++) s[c] = b2[c];
    const float* hp = g_h2 + (size_t)b * C2 * HW + r;
    for (int ci = 0; ci < C2; ci++) {
        float v = hp[(size_t)ci * HW];
#pragma unroll
        for (int c = 0; c < NCLS; c++) s[c] += v * __ldg(w2 + c * C2 + ci);
    }
#pragma unroll
    for (int c = 0; c < NCLS; c++)
        g_score[(size_t)(b * NCLS + c) * HW + r] = s[c];
}

// =====================================================================
// bilinear upsample x8, align-corners (matches reference f32 grid math)
// =====================================================================
__global__ void upsample_kernel(float* __restrict__ out)
{
    int idx = blockIdx.x * blockDim.x + threadIdx.x;
    if (idx >= SEG_ELEMS) return;
    int ow = idx % 800;
    int t  = idx / 800;
    int oh = t % 288;
    int plane = t / 288;  // b*5 + c

    const float SHs = (float)(35.0 / 287.0);
    const float SWs = (float)(99.0 / 799.0);
    float ph = (float)oh * SHs;
    int i0 = (int)ph; if (i0 > 34) i0 = 34;
    float fh = ph - (float)i0;
    float pw = (float)ow * SWs;
    int j0 = (int)pw; if (j0 > 98) j0 = 98;
    float fw = pw - (float)j0;

    const float* sp = g_score + (size_t)plane * HW + i0 * WW + j0;
    float v00 = sp[0], v01 = sp[1], v10 = sp[WW], v11 = sp[WW + 1];
    float c0 = v00 * (1.f - fh) + v10 * fh;
    float c1 = v01 * (1.f - fh) + v11 * fh;
    out[idx] = c0 * (1.f - fw) + c1 * fw;
}

// =====================================================================
// softmax over 5 channels + 2x2 avg pool -> (8, 5, 18, 50) flattened
// =====================================================================
__global__ void pool_kernel()
{
    int t = blockIdx.x * blockDim.x + threadIdx.x;
    if (t >= NB * 18 * 50) return;
    int w2_ = t % 50;
    int h2_ = (t / 50) % 18;
    int b   = t / 900;
    float ac[NCLS] = {0, 0, 0, 0, 0};
#pragma unroll
    for (int dy = 0; dy < 2; dy++)
#pragma unroll
        for (int dx = 0; dx < 2; dx++) {
            int r = (h2_ * 2 + dy) * WW + (w2_ * 2 + dx);
            float sc[NCLS];
            float mx = -1e30f;
#pragma unroll
            for (int c = 0; c < NCLS; c++) {
                sc[c] = g_score[(size_t)(b * NCLS + c) * HW + r];
                mx = fmaxf(mx, sc[c]);
            }
            float sum = 0.f;
#pragma unroll
            for (int c = 0; c < NCLS; c++) { sc[c] = expf(sc[c] - mx); sum += sc[c]; }
            float inv = 1.f / sum;
#pragma unroll
            for (int c = 0; c < NCLS; c++) ac[c] += sc[c] * inv;
        }
#pragma unroll
    for (int c = 0; c < NCLS; c++)
        g_pool[(size_t)b * 4500 + c * 900 + h2_ * 50 + w2_] = ac[c] * 0.25f;
}

// =====================================================================
// fc1: (8,4500) @ (4500,128)^T + bias, relu
// =====================================================================
__global__ __launch_bounds__(128)
void fc1_kernel(const float* __restrict__ w, const float* __restrict__ bias)
{
    __shared__ float sp[4500];
    int b = blockIdx.x, j = threadIdx.x;
    for (int i = j; i < 4500; i += 128) sp[i] = g_pool[(size_t)b * 4500 + i];
    __syncthreads();
    float acc = bias[j];
    const float* wr = w + (size_t)j * 4500;
    for (int i = 0; i < 4500; i += 4) {
        float4 wv = *(const float4*)(wr + i);
        acc += wv.x * sp[i] + wv.y * sp[i + 1] + wv.z * sp[i + 2] + wv.w * sp[i + 3];
    }
    g_f1[b * 128 + j] = fmaxf(acc, 0.f);
}

// =====================================================================
// fc2 + sigmoid -> exist_pred (8,4)
// =====================================================================
__global__ void fc2_kernel(const float* __restrict__ w, const float* __restrict__ bias,
                           float* __restrict__ out)
{
    int t = threadIdx.x;
    if (t >= 32) return;
    int b = t >> 2, o = t & 3;
    float acc = bias[o];
    const float* wr = w + o * 128;
    const float* f  = g_f1 + b * 128;
    for (int i = 0; i < 128; i++) acc += wr[i] * f[i];
    out[b * 4 + o] = 1.f / (1.f + expf(-acc));
}

// =====================================================================
// launch
// =====================================================================
extern "C" void kernel_launch(void* const* d_in, const int* in_sizes, int n_in,
                              void* d_out, int out_size)
{
    const float* x    = (const float*)d_in[0];
    const float* w1a  = (const float*)d_in[1];
    const float* bn1g = (const float*)d_in[2];
    const float* bn1b = (const float*)d_in[3];
    const float* bn1m = (const float*)d_in[4];
    const float* bn1v = (const float*)d_in[5];
    const float* w1b  = (const float*)d_in[6];
    const float* bn2g = (const float*)d_in[7];
    const float* bn2b = (const float*)d_in[8];
    const float* bn2m = (const float*)d_in[9];
    const float* bn2v = (const float*)d_in[10];
    const float* w_ud = (const float*)d_in[11];
    const float* w_du = (const float*)d_in[12];
    const float* w_lr = (const float*)d_in[13];
    const float* w_rl = (const float*)d_in[14];
    const float* w2   = (const float*)d_in[15];
    const float* b2   = (const float*)d_in[16];
    const float* fc1w = (const float*)d_in[17];
    const float* fc1b = (const float*)d_in[18];
    const float* fc2w = (const float*)d_in[19];
    const float* fc2b = (const float*)d_in[20];
    float* out = (float*)d_out;

    cudaFuncSetAttribute(msg_step_kernel<100, 224>,
                         cudaFuncAttributeMaxDynamicSharedMemorySize, MSG_SMEM_100);
    cudaFuncSetAttribute(msg_step_kernel<36, 96>,
                         cudaFuncAttributeMaxDynamicSharedMemorySize, MSG_SMEM_36);

    conv1_kernel<<<dim3(225, 8), 256>>>(x, w1a, bn1g, bn1b, bn1m, bn1v);
    conv2_kernel<<<dim3(225, 1), 256>>>(w1b, bn2g, bn2b, bn2m, bn2v);

    // message passes (sequential scans, in-place on g_h2)
    for (int r = 1; r < 36; r++)
        msg_step_kernel<100, 224><<<dim3(8, 16), 224, MSG_SMEM_100>>>(w_ud, (r - 1) * 100, r * 100, 1);
    for (int r = 34; r >= 0; r--)
        msg_step_kernel<100, 224><<<dim3(8, 16), 224, MSG_SMEM_100>>>(w_du, (r + 1) * 100, r * 100, 1);
    for (int c = 1; c < 100; c++)
        msg_step_kernel<36, 96><<<dim3(8, 16), 96, MSG_SMEM_36>>>(w_lr, c - 1, c, 100);
    for (int c = 98; c >= 0; c--)
        msg_step_kernel<36, 96><<<dim3(8, 16), 96, MSG_SMEM_36>>>(w_rl, c + 1, c, 100);

    head_kernel<<<(NPIX + 255) / 256, 256>>>(w2, b2);
    upsample_kernel<<<(SEG_ELEMS + 255) / 256, 256>>>(out);
    pool_kernel<<<(NB * 900 + 255) / 256, 256>>>();
    fc1_kernel<<<NB, 128>>>(fc1w, fc1b);
    fc2_kernel<<<1, 32>>>(fc2w, fc2b, out + SEG_ELEMS);
}

// round 5
// speedup vs baseline: 1.0270x; 1.0270x over previous
#include <cuda_runtime.h>
#include <math.h>

// ---------------- problem constants ----------------
#define NB   8
#define HH   36
#define WW   100
#define HW   3600      // 36*100
#define C0   512
#define C1   1024
#define C2   128
#define NCLS 5
#define NPIX 28800     // NB*HW
#define K1   4608      // 512*9
#define SEG_ELEMS 9216000  // 8*5*288*800

// ---------------- scratch (device globals; no allocation allowed) ----------------
__device__ __align__(16) float g_h1[NB * C1 * HW];     // conv1 output (8,1024,36,100)
__device__ __align__(16) float g_h2[NB * C2 * HW];     // conv2 / message-pass state (8,128,36,100)
__device__ __align__(16) float g_score[NB * NCLS * HW];// head conv output (8,5,36,100)
__device__ __align__(16) float g_pool[NB * 4500];      // softmax+pool features
__device__ __align__(16) float g_f1[NB * 128];         // fc1 output

// per-batch grid barrier state (count resets to 0 each barrier; gen monotonic)
__device__ unsigned g_bar_count[NB];
__device__ unsigned g_bar_gen[NB];

// =====================================================================
// conv1: dilated 3x3 (dil=4, pad=4), 512->1024, + BN1 + ReLU
// GEMM: M=1024 (co), N=28800 (pixels), K=4608 (ci*9). 128x128x8 tiles,
// double-buffered smem (1 sync per K-tile), incremental gather indices.
// =====================================================================
__global__ __launch_bounds__(256, 2)
void conv1_kernel(const float* __restrict__ x, const float* __restrict__ w,
                  const float* __restrict__ bg, const float* __restrict__ bb,
                  const float* __restrict__ bm, const float* __restrict__ bv)
{
    __shared__ float As[2][8][128];
    __shared__ float Bs[2][8][128];
    const int n0 = blockIdx.x * 128;
    const int m0 = blockIdx.y * 128;
    const int t  = threadIdx.x;
    const int tx = t & 15, ty = t >> 4;

    // B-load mapping: 8 k-rows x 128 n-cols, each thread one float4 of n
    const int bk  = t >> 5;
    const int bn4 = (t & 31) << 2;
    int pb[4], poh[4], pow_[4];
#pragma unroll
    for (int i = 0; i < 4; i++) {
        int n = n0 + bn4 + i;
        pb[i] = n / HW;
        int r = n - pb[i] * HW;
        poh[i] = r / WW;
        pow_[i] = r - poh[i] * WW;
    }
    // A-load mapping
    const int aRow = t >> 1;
    const int aCol = (t & 1) << 2;
    const float* aPtr = w + (size_t)(m0 + aRow) * K1 + aCol;

    // incremental gather state for k = k0 + bk (k0 starts at 0, bk < 8)
    int ci = 0, kk = bk;

    float acc[8][8];
#pragma unroll
    for (int i = 0; i < 8; i++)
#pragma unroll
        for (int j = 0; j < 8; j++) acc[i][j] = 0.f;

    // prologue: load tile 0 into buffer 0
    {
        float4 av = __ldg((const float4*)aPtr);
        As[0][aCol + 0][aRow] = av.x;
        As[0][aCol + 1][aRow] = av.y;
        As[0][aCol + 2][aRow] = av.z;
        As[0][aCol + 3][aRow] = av.w;
        int kh = kk / 3, kwv = kk - kh * 3;
        int dh = kh * 4 - 4, dw = kwv * 4 - 4;
        float tv[4];
#pragma unroll
        for (int i = 0; i < 4; i++) {
            int ih = poh[i] + dh, iw = pow_[i] + dw;
            float v = 0.f;
            if ((unsigned)ih < (unsigned)HH && (unsigned)iw < (unsigned)WW)
                v = __ldg(x + ((size_t)(pb[i] * C0 + ci) * HH + ih) * WW + iw);
            tv[i] = v;
        }
        *(float4*)&Bs[0][bk][bn4] = make_float4(tv[0], tv[1], tv[2], tv[3]);
    }
    __syncthreads();

    int buf = 0;
    for (int k0 = 0; k0 < K1; k0 += 8) {
        float4 avN;
        float  tvN[4];
        const bool more = (k0 + 8) < K1;
        if (more) {
            avN = __ldg((const float4*)(aPtr + k0 + 8));
            // advance (ci,kk) from k to k+8
            if (kk == 0) kk = 8; else { kk -= 1; ci += 1; }
            int kh = kk / 3, kwv = kk - kh * 3;
            int dh = kh * 4 - 4, dw = kwv * 4 - 4;
#pragma unroll
            for (int i = 0; i < 4; i++) {
                int ih = poh[i] + dh, iw = pow_[i] + dw;
                float v = 0.f;
                if ((unsigned)ih < (unsigned)HH && (unsigned)iw < (unsigned)WW)
                    v = __ldg(x + ((size_t)(pb[i] * C0 + ci) * HH + ih) * WW + iw);
                tvN[i] = v;
            }
        }

#pragma unroll
        for (int kk2 = 0; kk2 < 8; kk2++) {
            float ar[8], br[8];
#pragma unroll
            for (int i = 0; i < 8; i++) ar[i] = As[buf][kk2][ty * 8 + i];
#pragma unroll
            for (int j = 0; j < 8; j++) br[j] = Bs[buf][kk2][tx * 8 + j];
#pragma unroll
            for (int i = 0; i < 8; i++)
#pragma unroll
                for (int j = 0; j < 8; j++) acc[i][j] += ar[i] * br[j];
        }

        if (more) {
            int nb = buf ^ 1;
            As[nb][aCol + 0][aRow] = avN.x;
            As[nb][aCol + 1][aRow] = avN.y;
            As[nb][aCol + 2][aRow] = avN.z;
            As[nb][aCol + 3][aRow] = avN.w;
            *(float4*)&Bs[nb][bk][bn4] = make_float4(tvN[0], tvN[1], tvN[2], tvN[3]);
        }
        __syncthreads();
        buf ^= 1;
    }

#pragma unroll
    for (int i = 0; i < 8; i++) {
        int co = m0 + ty * 8 + i;
        float s    = bg[co] / sqrtf(bv[co] + 1e-5f);
        float bias = bb[co] - bm[co] * s;
#pragma unroll
        for (int j = 0; j < 8; j++) {
            int n  = n0 + tx * 8 + j;
            int b_ = n / HW;
            int r  = n - b_ * HW;
            float v = acc[i][j] * s + bias;
            g_h1[(size_t)(b_ * C1 + co) * HW + r] = fmaxf(v, 0.f);
        }
    }
}

// =====================================================================
// conv2: 1x1, 1024->128, + BN2 + ReLU. GEMM M=128, N=28800, K=1024.
// =====================================================================
__global__ __launch_bounds__(256)
void conv2_kernel(const float* __restrict__ w,
                  const float* __restrict__ bg, const float* __restrict__ bb,
                  const float* __restrict__ bm, const float* __restrict__ bv)
{
    __shared__ float As[8][128];
    __shared__ float Bs[8][128];
    const int n0 = blockIdx.x * 128;
    const int t  = threadIdx.x;
    const int tx = t & 15, ty = t >> 4;

    const int bk  = t >> 5;
    const int bn4 = (t & 31) << 2;
    int pb[4], pr[4];
#pragma unroll
    for (int i = 0; i < 4; i++) {
        int n = n0 + bn4 + i;
        pb[i] = n / HW;
        pr[i] = n - pb[i] * HW;
    }
    const int aRow = t >> 1;
    const int aCol = (t & 1) << 2;
    const float* aPtr = w + (size_t)aRow * C1 + aCol;

    float acc[8][8];
#pragma unroll
    for (int i = 0; i < 8; i++)
#pragma unroll
        for (int j = 0; j < 8; j++) acc[i][j] = 0.f;

    for (int k0 = 0; k0 < C1; k0 += 8) {
        float4 av = *(const float4*)(aPtr + k0);
        As[aCol + 0][aRow] = av.x;
        As[aCol + 1][aRow] = av.y;
        As[aCol + 2][aRow] = av.z;
        As[aCol + 3][aRow] = av.w;

        int k = k0 + bk;
        float tv[4];
#pragma unroll
        for (int i = 0; i < 4; i++)
            tv[i] = g_h1[(size_t)(pb[i] * C1 + k) * HW + pr[i]];
        *(float4*)&Bs[bk][bn4] = make_float4(tv[0], tv[1], tv[2], tv[3]);
        __syncthreads();

#pragma unroll
        for (int kk2 = 0; kk2 < 8; kk2++) {
            float ar[8], br[8];
#pragma unroll
            for (int i = 0; i < 8; i++) ar[i] = As[kk2][ty * 8 + i];
#pragma unroll
            for (int j = 0; j < 8; j++) br[j] = Bs[kk2][tx * 8 + j];
#pragma unroll
            for (int i = 0; i < 8; i++)
#pragma unroll
                for (int j = 0; j < 8; j++) acc[i][j] += ar[i] * br[j];
        }
        __syncthreads();
    }

#pragma unroll
    for (int i = 0; i < 8; i++) {
        int co = ty * 8 + i;
        float s    = bg[co] / sqrtf(bv[co] + 1e-5f);
        float bias = bb[co] - bm[co] * s;
#pragma unroll
        for (int j = 0; j < 8; j++) {
            int n  = n0 + tx * 8 + j;
            int b_ = n / HW;
            int r  = n - b_ * HW;
            float v = acc[i][j] * s + bias;
            g_h2[(size_t)(b_ * C2 + co) * HW + r] = fmaxf(v, 0.f);
        }
    }
}

// =====================================================================
// persistent scan kernel: one launch per direction.
// Grid: (NB batches, NBLK co-groups of COB). All blocks co-resident
// (grid <= 128 <= 148 SMs). Steps separated by per-batch spin barrier.
// Weights cached in smem once. prev row re-read via __ldcg (L2, no stale L1).
// =====================================================================
__device__ __forceinline__ void batch_barrier(int b, unsigned nb)
{
    __syncthreads();
    if (threadIdx.x == 0) {
        __threadfence();
        volatile unsigned* genp = &g_bar_gen[b];
        unsigned my = *genp;
        unsigned a  = atomicAdd(&g_bar_count[b], 1u);
        if (a == nb - 1u) {
            atomicExch(&g_bar_count[b], 0u);
            __threadfence();
            *genp = my + 1u;
        } else {
            while (*genp == my) { __nanosleep(64); }
        }
        __threadfence();
    }
    __syncthreads();
}

template <int L, int COB, int NBLK>
__global__ __launch_bounds__(224, 1)
void scan_kernel(const float* __restrict__ wgt, int nSteps,
                 int prevOff0, int curOff0, int dOff, int posStride)
{
    constexpr int THREADS = 224;
    constexpr int LP = L + 8;
    extern __shared__ float sm[];
    float* prev = sm;                // 128 * LP
    float* ws   = sm + 128 * LP;     // COB * 128 * 9

    const int b   = blockIdx.x;
    const int cog = blockIdx.y * COB;
    const int tid = threadIdx.x;

    // load weights once
    for (int i = tid; i < COB * 128 * 9; i += THREADS)
        ws[i] = __ldg(wgt + (size_t)cog * 128 * 9 + i);

    constexpr int NSEG = L / 4;
    constexpr int NT   = COB * NSEG;
    const int co = tid / NSEG;
    const int p0 = (tid - co * NSEG) * 4;

    int prevOff = prevOff0, curOff = curOff0;
    for (int s = 0; s < nSteps; s++) {
        if (s) batch_barrier(b, NBLK);
        else   __syncthreads();   // weights visible

        // stage prev slice (zero-padded by 4 on each end)
        for (int i = tid; i < 128 * LP; i += THREADS) {
            int ci = i / LP;
            int p  = i - ci * LP - 4;
            float v = 0.f;
            if ((unsigned)p < (unsigned)L)
                v = __ldcg(&g_h2[(size_t)(b * C2 + ci) * HW + prevOff + p * posStride]);
            prev[i] = v;
        }
        __syncthreads();

        if (tid < NT) {
            float acc0 = 0.f, acc1 = 0.f, acc2 = 0.f, acc3 = 0.f;
            const float* wbase = ws + (size_t)co * 128 * 9;
            for (int ci = 0; ci < 128; ci++) {
                const float4* pr4 = (const float4*)(prev + ci * LP + p0);
                float4 a0 = pr4[0], a1 = pr4[1], a2 = pr4[2];
                float xv[12] = {a0.x, a0.y, a0.z, a0.w,
                                a1.x, a1.y, a1.z, a1.w,
                                a2.x, a2.y, a2.z, a2.w};
                const float* wp = wbase + ci * 9;
#pragma unroll
                for (int k = 0; k < 9; k++) {
                    float wk = wp[k];
                    acc0 += xv[k]     * wk;
                    acc1 += xv[k + 1] * wk;
                    acc2 += xv[k + 2] * wk;
                    acc3 += xv[k + 3] * wk;
                }
            }
            const size_t base = (size_t)(b * C2 + cog + co) * HW + curOff;
            float* o0 = &g_h2[base + (size_t)(p0 + 0) * posStride];
            float* o1 = &g_h2[base + (size_t)(p0 + 1) * posStride];
            float* o2 = &g_h2[base + (size_t)(p0 + 2) * posStride];
            float* o3 = &g_h2[base + (size_t)(p0 + 3) * posStride];
            *o0 = __ldcg(o0) + fmaxf(acc0, 0.f);
            *o1 = __ldcg(o1) + fmaxf(acc1, 0.f);
            *o2 = __ldcg(o2) + fmaxf(acc2, 0.f);
            *o3 = __ldcg(o3) + fmaxf(acc3, 0.f);
        }
        prevOff += dOff;
        curOff  += dOff;
    }
}

#define SCAN_SMEM_UD ((128 * 108 + 8  * 128 * 9) * 4)   // 92,160 B
#define SCAN_SMEM_LR ((128 * 44  + 16 * 128 * 9) * 4)   // 96,256 B

// =====================================================================
// head: 1x1 conv 128->5 + bias
// =====================================================================
__global__ void head_kernel(const float* __restrict__ w2, const float* __restrict__ b2)
{
    int n = blockIdx.x * blockDim.x + threadIdx.x;
    if (n >= NPIX) return;
    int b = n / HW;
    int r = n - b * HW;
    float s[NCLS];
#pragma unroll
    for (int c = 0; c < NCLS; c++) s[c] = b2[c];
    const float* hp = g_h2 + (size_t)b * C2 * HW + r;
    for (int ci = 0; ci < C2; ci++) {
        float v = hp[(size_t)ci * HW];
#pragma unroll
        for (int c = 0; c < NCLS; c++) s[c] += v * __ldg(w2 + c * C2 + ci);
    }
#pragma unroll
    for (int c = 0; c < NCLS; c++)
        g_score[(size_t)(b * NCLS + c) * HW + r] = s[c];
}

// =====================================================================
// bilinear upsample x8, align-corners
// =====================================================================
__global__ void upsample_kernel(float* __restrict__ out)
{
    int idx = blockIdx.x * blockDim.x + threadIdx.x;
    if (idx >= SEG_ELEMS) return;
    int ow = idx % 800;
    int t  = idx / 800;
    int oh = t % 288;
    int plane = t / 288;  // b*5 + c

    const float SHs = (float)(35.0 / 287.0);
    const float SWs = (float)(99.0 / 799.0);
    float ph = (float)oh * SHs;
    int i0 = (int)ph; if (i0 > 34) i0 = 34;
    float fh = ph - (float)i0;
    float pw = (float)ow * SWs;
    int j0 = (int)pw; if (j0 > 98) j0 = 98;
    float fw = pw - (float)j0;

    const float* sp = g_score + (size_t)plane * HW + i0 * WW + j0;
    float v00 = sp[0], v01 = sp[1], v10 = sp[WW], v11 = sp[WW + 1];
    float c0 = v00 * (1.f - fh) + v10 * fh;
    float c1 = v01 * (1.f - fh) + v11 * fh;
    out[idx] = c0 * (1.f - fw) + c1 * fw;
}

// =====================================================================
// softmax over 5 channels + 2x2 avg pool -> (8, 5, 18, 50) flattened
// =====================================================================
__global__ void pool_kernel()
{
    int t = blockIdx.x * blockDim.x + threadIdx.x;
    if (t >= NB * 18 * 50) return;
    int w2_ = t % 50;
    int h2_ = (t / 50) % 18;
    int b   = t / 900;
    float ac[NCLS] = {0, 0, 0, 0, 0};
#pragma unroll
    for (int dy = 0; dy < 2; dy++)
#pragma unroll
        for (int dx = 0; dx < 2; dx++) {
            int r = (h2_ * 2 + dy) * WW + (w2_ * 2 + dx);
            float sc[NCLS];
            float mx = -1e30f;
#pragma unroll
            for (int c = 0; c < NCLS; c++) {
                sc[c] = g_score[(size_t)(b * NCLS + c) * HW + r];
                mx = fmaxf(mx, sc[c]);
            }
            float sum = 0.f;
#pragma unroll
            for (int c = 0; c < NCLS; c++) { sc[c] = expf(sc[c] - mx); sum += sc[c]; }
            float inv = 1.f / sum;
#pragma unroll
            for (int c = 0; c < NCLS; c++) ac[c] += sc[c] * inv;
        }
#pragma unroll
    for (int c = 0; c < NCLS; c++)
        g_pool[(size_t)b * 4500 + c * 900 + h2_ * 50 + w2_] = ac[c] * 0.25f;
}

// =====================================================================
// fc1: (8,4500) @ (4500,128)^T + bias, relu
// =====================================================================
__global__ __launch_bounds__(128)
void fc1_kernel(const float* __restrict__ w, const float* __restrict__ bias)
{
    __shared__ float sp[4500];
    int b = blockIdx.x, j = threadIdx.x;
    for (int i = j; i < 4500; i += 128) sp[i] = g_pool[(size_t)b * 4500 + i];
    __syncthreads();
    float acc = bias[j];
    const float* wr = w + (size_t)j * 4500;
    for (int i = 0; i < 4500; i += 4) {
        float4 wv = *(const float4*)(wr + i);
        acc += wv.x * sp[i] + wv.y * sp[i + 1] + wv.z * sp[i + 2] + wv.w * sp[i + 3];
    }
    g_f1[b * 128 + j] = fmaxf(acc, 0.f);
}

// =====================================================================
// fc2 + sigmoid -> exist_pred (8,4)
// =====================================================================
__global__ void fc2_kernel(const float* __restrict__ w, const float* __restrict__ bias,
                           float* __restrict__ out)
{
    int t = threadIdx.x;
    if (t >= 32) return;
    int b = t >> 2, o = t & 3;
    float acc = bias[o];
    const float* wr = w + o * 128;
    const float* f  = g_f1 + b * 128;
    for (int i = 0; i < 128; i++) acc += wr[i] * f[i];
    out[b * 4 + o] = 1.f / (1.f + expf(-acc));
}

// =====================================================================
// launch
// =====================================================================
extern "C" void kernel_launch(void* const* d_in, const int* in_sizes, int n_in,
                              void* d_out, int out_size)
{
    const float* x    = (const float*)d_in[0];
    const float* w1a  = (const float*)d_in[1];
    const float* bn1g = (const float*)d_in[2];
    const float* bn1b = (const float*)d_in[3];
    const float* bn1m = (const float*)d_in[4];
    const float* bn1v = (const float*)d_in[5];
    const float* w1b  = (const float*)d_in[6];
    const float* bn2g = (const float*)d_in[7];
    const float* bn2b = (const float*)d_in[8];
    const float* bn2m = (const float*)d_in[9];
    const float* bn2v = (const float*)d_in[10];
    const float* w_ud = (const float*)d_in[11];
    const float* w_du = (const float*)d_in[12];
    const float* w_lr = (const float*)d_in[13];
    const float* w_rl = (const float*)d_in[14];
    const float* w2   = (const float*)d_in[15];
    const float* b2   = (const float*)d_in[16];
    const float* fc1w = (const float*)d_in[17];
    const float* fc1b = (const float*)d_in[18];
    const float* fc2w = (const float*)d_in[19];
    const float* fc2b = (const float*)d_in[20];
    float* out = (float*)d_out;

    cudaFuncSetAttribute(scan_kernel<100, 8, 16>,
                         cudaFuncAttributeMaxDynamicSharedMemorySize, SCAN_SMEM_UD);
    cudaFuncSetAttribute(scan_kernel<36, 16, 8>,
                         cudaFuncAttributeMaxDynamicSharedMemorySize, SCAN_SMEM_LR);

    conv1_kernel<<<dim3(225, 8), 256>>>(x, w1a, bn1g, bn1b, bn1m, bn1v);
    conv2_kernel<<<dim3(225, 1), 256>>>(w1b, bn2g, bn2b, bn2m, bn2v);

    // message passes: 4 persistent launches (in-place on g_h2)
    scan_kernel<100, 8, 16><<<dim3(8, 16), 224, SCAN_SMEM_UD>>>(w_ud, 35,    0,  100,  100, 1);
    scan_kernel<100, 8, 16><<<dim3(8, 16), 224, SCAN_SMEM_UD>>>(w_du, 35, 3500, 3400, -100, 1);
    scan_kernel<36, 16, 8><<<dim3(8, 8), 224, SCAN_SMEM_LR>>>(w_lr, 99,    0,    1,    1, 100);
    scan_kernel<36, 16, 8><<<dim3(8, 8), 224, SCAN_SMEM_LR>>>(w_rl, 99,   99,   98,   -1, 100);

    head_kernel<<<(NPIX + 255) / 256, 256>>>(w2, b2);
    upsample_kernel<<<(SEG_ELEMS + 255) / 256, 256>>>(out);
    pool_kernel<<<(NB * 900 + 255) / 256, 256>>>();
    fc1_kernel<<<NB, 128>>>(fc1w, fc1b);
    fc2_kernel<<<1, 32>>>(fc2w, fc2b, out + SEG_ELEMS);
}

// round 8
// speedup vs baseline: 1.0273x; 1.0003x over previous
#include <cuda_runtime.h>
#include <math.h>

// ---------------- problem constants ----------------
#define NB   8
#define HH   36
#define WW   100
#define HW   3600      // 36*100
#define C0   512
#define C1   1024
#define C2   128
#define NCLS 5
#define NPIX 28800     // NB*HW
#define K1   4608      // 512*9
#define SEG_ELEMS 9216000  // 8*5*288*800

// ---------------- scratch (device globals; no allocation allowed) ----------------
__device__ __align__(16) float g_h1[NB * C1 * HW];     // conv1 output (8,1024,36,100)
__device__ __align__(16) float g_h2[NB * C2 * HW];     // conv2 / message-pass state (8,128,36,100)
__device__ __align__(16) float g_score[NB * NCLS * HW];// head conv output (8,5,36,100)
__device__ __align__(16) float g_pool[NB * 4500];      // softmax+pool features
__device__ __align__(16) float g_f1[NB * 128];         // fc1 output

// per-batch grid barrier state (count resets to 0 each barrier; gen monotonic)
__device__ unsigned g_bar_count[NB];
__device__ unsigned g_bar_gen[NB];

// =====================================================================
// conv1: dilated 3x3 (dil=4, pad=4), 512->1024, + BN1 + ReLU
// GEMM: M=1024 (co), N=28800 (pixels), K=4608 (ci*9). 128x128x8 tiles,
// double-buffered smem (1 sync per K-tile), incremental gather indices.
// =====================================================================
__global__ __launch_bounds__(256, 2)
void conv1_kernel(const float* __restrict__ x, const float* __restrict__ w,
                  const float* __restrict__ bg, const float* __restrict__ bb,
                  const float* __restrict__ bm, const float* __restrict__ bv)
{
    __shared__ float As[2][8][128];
    __shared__ float Bs[2][8][128];
    const int n0 = blockIdx.x * 128;
    const int m0 = blockIdx.y * 128;
    const int t  = threadIdx.x;
    const int tx = t & 15, ty = t >> 4;

    // B-load mapping: 8 k-rows x 128 n-cols, each thread one float4 of n
    const int bk  = t >> 5;
    const int bn4 = (t & 31) << 2;
    int pb[4], poh[4], pow_[4];
#pragma unroll
    for (int i = 0; i < 4; i++) {
        int n = n0 + bn4 + i;
        pb[i] = n / HW;
        int r = n - pb[i] * HW;
        poh[i] = r / WW;
        pow_[i] = r - poh[i] * WW;
    }
    // A-load mapping
    const int aRow = t >> 1;
    const int aCol = (t & 1) << 2;
    const float* aPtr = w + (size_t)(m0 + aRow) * K1 + aCol;

    // incremental gather state for k = k0 + bk (k0 starts at 0, bk < 8)
    int ci = 0, kk = bk;

    float acc[8][8];
#pragma unroll
    for (int i = 0; i < 8; i++)
#pragma unroll
        for (int j = 0; j < 8; j++) acc[i][j] = 0.f;

    // prologue: load tile 0 into buffer 0
    {
        float4 av = __ldg((const float4*)aPtr);
        As[0][aCol + 0][aRow] = av.x;
        As[0][aCol + 1][aRow] = av.y;
        As[0][aCol + 2][aRow] = av.z;
        As[0][aCol + 3][aRow] = av.w;
        int kh = kk / 3, kwv = kk - kh * 3;
        int dh = kh * 4 - 4, dw = kwv * 4 - 4;
        float tv[4];
#pragma unroll
        for (int i = 0; i < 4; i++) {
            int ih = poh[i] + dh, iw = pow_[i] + dw;
            float v = 0.f;
            if ((unsigned)ih < (unsigned)HH && (unsigned)iw < (unsigned)WW)
                v = __ldg(x + ((size_t)(pb[i] * C0 + ci) * HH + ih) * WW + iw);
            tv[i] = v;
        }
        *(float4*)&Bs[0][bk][bn4] = make_float4(tv[0], tv[1], tv[2], tv[3]);
    }
    __syncthreads();

    int buf = 0;
    for (int k0 = 0; k0 < K1; k0 += 8) {
        float4 avN;
        float  tvN[4];
        const bool more = (k0 + 8) < K1;
        if (more) {
            avN = __ldg((const float4*)(aPtr + k0 + 8));
            // advance (ci,kk) from k to k+8
            if (kk == 0) kk = 8; else { kk -= 1; ci += 1; }
            int kh = kk / 3, kwv = kk - kh * 3;
            int dh = kh * 4 - 4, dw = kwv * 4 - 4;
#pragma unroll
            for (int i = 0; i < 4; i++) {
                int ih = poh[i] + dh, iw = pow_[i] + dw;
                float v = 0.f;
                if ((unsigned)ih < (unsigned)HH && (unsigned)iw < (unsigned)WW)
                    v = __ldg(x + ((size_t)(pb[i] * C0 + ci) * HH + ih) * WW + iw);
                tvN[i] = v;
            }
        }

#pragma unroll
        for (int kk2 = 0; kk2 < 8; kk2++) {
            float ar[8], br[8];
#pragma unroll
            for (int i = 0; i < 8; i++) ar[i] = As[buf][kk2][ty * 8 + i];
#pragma unroll
            for (int j = 0; j < 8; j++) br[j] = Bs[buf][kk2][tx * 8 + j];
#pragma unroll
            for (int i = 0; i < 8; i++)
#pragma unroll
                for (int j = 0; j < 8; j++) acc[i][j] += ar[i] * br[j];
        }

        if (more) {
            int nb = buf ^ 1;
            As[nb][aCol + 0][aRow] = avN.x;
            As[nb][aCol + 1][aRow] = avN.y;
            As[nb][aCol + 2][aRow] = avN.z;
            As[nb][aCol + 3][aRow] = avN.w;
            *(float4*)&Bs[nb][bk][bn4] = make_float4(tvN[0], tvN[1], tvN[2], tvN[3]);
        }
        __syncthreads();
        buf ^= 1;
    }

#pragma unroll
    for (int i = 0; i < 8; i++) {
        int co = m0 + ty * 8 + i;
        float s    = bg[co] / sqrtf(bv[co] + 1e-5f);
        float bias = bb[co] - bm[co] * s;
#pragma unroll
        for (int j = 0; j < 8; j++) {
            int n  = n0 + tx * 8 + j;
            int b_ = n / HW;
            int r  = n - b_ * HW;
            float v = acc[i][j] * s + bias;
            g_h1[(size_t)(b_ * C1 + co) * HW + r] = fmaxf(v, 0.f);
        }
    }
}

// =====================================================================
// conv2: 1x1, 1024->128, + BN2 + ReLU. GEMM M=128, N=28800, K=1024.
// =====================================================================
__global__ __launch_bounds__(256)
void conv2_kernel(const float* __restrict__ w,
                  const float* __restrict__ bg, const float* __restrict__ bb,
                  const float* __restrict__ bm, const float* __restrict__ bv)
{
    __shared__ float As[8][128];
    __shared__ float Bs[8][128];
    const int n0 = blockIdx.x * 128;
    const int t  = threadIdx.x;
    const int tx = t & 15, ty = t >> 4;

    const int bk  = t >> 5;
    const int bn4 = (t & 31) << 2;
    int pb[4], pr[4];
#pragma unroll
    for (int i = 0; i < 4; i++) {
        int n = n0 + bn4 + i;
        pb[i] = n / HW;
        pr[i] = n - pb[i] * HW;
    }
    const int aRow = t >> 1;
    const int aCol = (t & 1) << 2;
    const float* aPtr = w + (size_t)aRow * C1 + aCol;

    float acc[8][8];
#pragma unroll
    for (int i = 0; i < 8; i++)
#pragma unroll
        for (int j = 0; j < 8; j++) acc[i][j] = 0.f;

    for (int k0 = 0; k0 < C1; k0 += 8) {
        float4 av = *(const float4*)(aPtr + k0);
        As[aCol + 0][aRow] = av.x;
        As[aCol + 1][aRow] = av.y;
        As[aCol + 2][aRow] = av.z;
        As[aCol + 3][aRow] = av.w;

        int k = k0 + bk;
        float tv[4];
#pragma unroll
        for (int i = 0; i < 4; i++)
            tv[i] = g_h1[(size_t)(pb[i] * C1 + k) * HW + pr[i]];
        *(float4*)&Bs[bk][bn4] = make_float4(tv[0], tv[1], tv[2], tv[3]);
        __syncthreads();

#pragma unroll
        for (int kk2 = 0; kk2 < 8; kk2++) {
            float ar[8], br[8];
#pragma unroll
            for (int i = 0; i < 8; i++) ar[i] = As[kk2][ty * 8 + i];
#pragma unroll
            for (int j = 0; j < 8; j++) br[j] = Bs[kk2][tx * 8 + j];
#pragma unroll
            for (int i = 0; i < 8; i++)
#pragma unroll
                for (int j = 0; j < 8; j++) acc[i][j] += ar[i] * br[j];
        }
        __syncthreads();
    }

#pragma unroll
    for (int i = 0; i < 8; i++) {
        int co = ty * 8 + i;
        float s    = bg[co] / sqrtf(bv[co] + 1e-5f);
        float bias = bb[co] - bm[co] * s;
#pragma unroll
        for (int j = 0; j < 8; j++) {
            int n  = n0 + tx * 8 + j;
            int b_ = n / HW;
            int r  = n - b_ * HW;
            float v = acc[i][j] * s + bias;
            g_h2[(size_t)(b_ * C2 + co) * HW + r] = fmaxf(v, 0.f);
        }
    }
}

// =====================================================================
// persistent scan kernel: one launch per direction.
// Grid: (NB batches, NBLK co-groups of COB). All blocks co-resident
// (grid <= 128 <= 148 SMs). Steps separated by per-batch spin barrier.
// Weights cached in smem once. prev row re-read via __ldcg (L2, no stale L1).
// =====================================================================
__device__ __forceinline__ void batch_barrier(int b, unsigned nb)
{
    __syncthreads();
    if (threadIdx.x == 0) {
        __threadfence();
        volatile unsigned* genp = &g_bar_gen[b];
        unsigned my = *genp;
        unsigned a  = atomicAdd(&g_bar_count[b], 1u);
        if (a == nb - 1u) {
            atomicExch(&g_bar_count[b], 0u);
            __threadfence();
            *genp = my + 1u;
        } else {
            while (*genp == my) { __nanosleep(64); }
        }
        __threadfence();
    }
    __syncthreads();
}

template <int L, int COB, int NBLK>
__global__ __launch_bounds__(224, 1)
void scan_kernel(const float* __restrict__ wgt, int nSteps,
                 int prevOff0, int curOff0, int dOff, int posStride)
{
    constexpr int THREADS = 224;
    constexpr int LP = L + 8;
    extern __shared__ float sm[];
    float* prev = sm;                // 128 * LP
    float* ws   = sm + 128 * LP;     // COB * 128 * 9

    const int b   = blockIdx.x;
    const int cog = blockIdx.y * COB;
    const int tid = threadIdx.x;

    // load weights once
    for (int i = tid; i < COB * 128 * 9; i += THREADS)
        ws[i] = __ldg(wgt + (size_t)cog * 128 * 9 + i);

    constexpr int NSEG = L / 4;
    constexpr int NT   = COB * NSEG;
    const int co = tid / NSEG;
    const int p0 = (tid - co * NSEG) * 4;

    int prevOff = prevOff0, curOff = curOff0;
    for (int s = 0; s < nSteps; s++) {
        if (s) batch_barrier(b, NBLK);
        else   __syncthreads();   // weights visible

        // stage prev slice (zero-padded by 4 on each end)
        for (int i = tid; i < 128 * LP; i += THREADS) {
            int ci = i / LP;
            int p  = i - ci * LP - 4;
            float v = 0.f;
            if ((unsigned)p < (unsigned)L)
                v = __ldcg(&g_h2[(size_t)(b * C2 + ci) * HW + prevOff + p * posStride]);
            prev[i] = v;
        }
        __syncthreads();

        if (tid < NT) {
            float acc0 = 0.f, acc1 = 0.f, acc2 = 0.f, acc3 = 0.f;
            const float* wbase = ws + (size_t)co * 128 * 9;
            for (int ci = 0; ci < 128; ci++) {
                const float4* pr4 = (const float4*)(prev + ci * LP + p0);
                float4 a0 = pr4[0], a1 = pr4[1], a2 = pr4[2];
                float xv[12] = {a0.x, a0.y, a0.z, a0.w,
                                a1.x, a1.y, a1.z, a1.w,
                                a2.x, a2.y, a2.z, a2.w};
                const float* wp = wbase + ci * 9;
#pragma unroll
                for (int k = 0; k < 9; k++) {
                    float wk = wp[k];
                    acc0 += xv[k]     * wk;
                    acc1 += xv[k + 1] * wk;
                    acc2 += xv[k + 2] * wk;
                    acc3 += xv[k + 3] * wk;
                }
            }
            const size_t base = (size_t)(b * C2 + cog + co) * HW + curOff;
            float* o0 = &g_h2[base + (size_t)(p0 + 0) * posStride];
            float* o1 = &g_h2[base + (size_t)(p0 + 1) * posStride];
            float* o2 = &g_h2[base + (size_t)(p0 + 2) * posStride];
            float* o3 = &g_h2[base + (size_t)(p0 + 3) * posStride];
            *o0 = __ldcg(o0) + fmaxf(acc0, 0.f);
            *o1 = __ldcg(o1) + fmaxf(acc1, 0.f);
            *o2 = __ldcg(o2) + fmaxf(acc2, 0.f);
            *o3 = __ldcg(o3) + fmaxf(acc3, 0.f);
        }
        prevOff += dOff;
        curOff  += dOff;
    }
}

#define SCAN_SMEM_UD ((128 * 108 + 8  * 128 * 9) * 4)   // 92,160 B
#define SCAN_SMEM_LR ((128 * 44  + 16 * 128 * 9) * 4)   // 96,256 B

// =====================================================================
// head: 1x1 conv 128->5 + bias
// =====================================================================
__global__ void head_kernel(const float* __restrict__ w2, const float* __restrict__ b2)
{
    int n = blockIdx.x * blockDim.x + threadIdx.x;
    if (n >= NPIX) return;
    int b = n / HW;
    int r = n - b * HW;
    float s[NCLS];
#pragma unroll
    for (int c = 0; c < NCLS; c++) s[c] = b2[c];
    const float* hp = g_h2 + (size_t)b * C2 * HW + r;
    for (int ci = 0; ci < C2; ci++) {
        float v = hp[(size_t)ci * HW];
#pragma unroll
        for (int c = 0; c < NCLS; c++) s[c] += v * __ldg(w2 + c * C2 + ci);
    }
#pragma unroll
    for (int c = 0; c < NCLS; c++)
        g_score[(size_t)(b * NCLS + c) * HW + r] = s[c];
}

// =====================================================================
// bilinear upsample x8, align-corners
// =====================================================================
__global__ void upsample_kernel(float* __restrict__ out)
{
    int idx = blockIdx.x * blockDim.x + threadIdx.x;
    if (idx >= SEG_ELEMS) return;
    int ow = idx % 800;
    int t  = idx / 800;
    int oh = t % 288;
    int plane = t / 288;  // b*5 + c

    const float SHs = (float)(35.0 / 287.0);
    const float SWs = (float)(99.0 / 799.0);
    float ph = (float)oh * SHs;
    int i0 = (int)ph; if (i0 > 34) i0 = 34;
    float fh = ph - (float)i0;
    float pw = (float)ow * SWs;
    int j0 = (int)pw; if (j0 > 98) j0 = 98;
    float fw = pw - (float)j0;

    const float* sp = g_score + (size_t)plane * HW + i0 * WW + j0;
    float v00 = sp[0], v01 = sp[1], v10 = sp[WW], v11 = sp[WW + 1];
    float c0 = v00 * (1.f - fh) + v10 * fh;
    float c1 = v01 * (1.f - fh) + v11 * fh;
    out[idx] = c0 * (1.f - fw) + c1 * fw;
}

// =====================================================================
// softmax over 5 channels + 2x2 avg pool -> (8, 5, 18, 50) flattened
// =====================================================================
__global__ void pool_kernel()
{
    int t = blockIdx.x * blockDim.x + threadIdx.x;
    if (t >= NB * 18 * 50) return;
    int w2_ = t % 50;
    int h2_ = (t / 50) % 18;
    int b   = t / 900;
    float ac[NCLS] = {0, 0, 0, 0, 0};
#pragma unroll
    for (int dy = 0; dy < 2; dy++)
#pragma unroll
        for (int dx = 0; dx < 2; dx++) {
            int r = (h2_ * 2 + dy) * WW + (w2_ * 2 + dx);
            float sc[NCLS];
            float mx = -1e30f;
#pragma unroll
            for (int c = 0; c < NCLS; c++) {
                sc[c] = g_score[(size_t)(b * NCLS + c) * HW + r];
                mx = fmaxf(mx, sc[c]);
            }
            float sum = 0.f;
#pragma unroll
            for (int c = 0; c < NCLS; c++) { sc[c] = expf(sc[c] - mx); sum += sc[c]; }
            float inv = 1.f / sum;
#pragma unroll
            for (int c = 0; c < NCLS; c++) ac[c] += sc[c] * inv;
        }
#pragma unroll
    for (int c = 0; c < NCLS; c++)
        g_pool[(size_t)b * 4500 + c * 900 + h2_ * 50 + w2_] = ac[c] * 0.25f;
}

// =====================================================================
// fc1: (8,4500) @ (4500,128)^T + bias, relu
// =====================================================================
__global__ __launch_bounds__(128)
void fc1_kernel(const float* __restrict__ w, const float* __restrict__ bias)
{
    __shared__ float sp[4500];
    int b = blockIdx.x, j = threadIdx.x;
    for (int i = j; i < 4500; i += 128) sp[i] = g_pool[(size_t)b * 4500 + i];
    __syncthreads();
    float acc = bias[j];
    const float* wr = w + (size_t)j * 4500;
    for (int i = 0; i < 4500; i += 4) {
        float4 wv = *(const float4*)(wr + i);
        acc += wv.x * sp[i] + wv.y * sp[i + 1] + wv.z * sp[i + 2] + wv.w * sp[i + 3];
    }
    g_f1[b * 128 + j] = fmaxf(acc, 0.f);
}

// =====================================================================
// fc2 + sigmoid -> exist_pred (8,4)
// =====================================================================
__global__ void fc2_kernel(const float* __restrict__ w, const float* __restrict__ bias,
                           float* __restrict__ out)
{
    int t = threadIdx.x;
    if (t >= 32) return;
    int b = t >> 2, o = t & 3;
    float acc = bias[o];
    const float* wr = w + o * 128;
    const float* f  = g_f1 + b * 128;
    for (int i = 0; i < 128; i++) acc += wr[i] * f[i];
    out[b * 4 + o] = 1.f / (1.f + expf(-acc));
}

// =====================================================================
// launch
// =====================================================================
extern "C" void kernel_launch(void* const* d_in, const int* in_sizes, int n_in,
                              void* d_out, int out_size)
{
    const float* x    = (const float*)d_in[0];
    const float* w1a  = (const float*)d_in[1];
    const float* bn1g = (const float*)d_in[2];
    const float* bn1b = (const float*)d_in[3];
    const float* bn1m = (const float*)d_in[4];
    const float* bn1v = (const float*)d_in[5];
    const float* w1b  = (const float*)d_in[6];
    const float* bn2g = (const float*)d_in[7];
    const float* bn2b = (const float*)d_in[8];
    const float* bn2m = (const float*)d_in[9];
    const float* bn2v = (const float*)d_in[10];
    const float* w_ud = (const float*)d_in[11];
    const float* w_du = (const float*)d_in[12];
    const float* w_lr = (const float*)d_in[13];
    const float* w_rl = (const float*)d_in[14];
    const float* w2   = (const float*)d_in[15];
    const float* b2   = (const float*)d_in[16];
    const float* fc1w = (const float*)d_in[17];
    const float* fc1b = (const float*)d_in[18];
    const float* fc2w = (const float*)d_in[19];
    const float* fc2b = (const float*)d_in[20];
    float* out = (float*)d_out;

    cudaFuncSetAttribute(scan_kernel<100, 8, 16>,
                         cudaFuncAttributeMaxDynamicSharedMemorySize, SCAN_SMEM_UD);
    cudaFuncSetAttribute(scan_kernel<36, 16, 8>,
                         cudaFuncAttributeMaxDynamicSharedMemorySize, SCAN_SMEM_LR);

    conv1_kernel<<<dim3(225, 8), 256>>>(x, w1a, bn1g, bn1b, bn1m, bn1v);
    conv2_kernel<<<dim3(225, 1), 256>>>(w1b, bn2g, bn2b, bn2m, bn2v);

    // message passes: 4 persistent launches (in-place on g_h2)
    scan_kernel<100, 8, 16><<<dim3(8, 16), 224, SCAN_SMEM_UD>>>(w_ud, 35,    0,  100,  100, 1);
    scan_kernel<100, 8, 16><<<dim3(8, 16), 224, SCAN_SMEM_UD>>>(w_du, 35, 3500, 3400, -100, 1);
    scan_kernel<36, 16, 8><<<dim3(8, 8), 224, SCAN_SMEM_LR>>>(w_lr, 99,    0,    1,    1, 100);
    scan_kernel<36, 16, 8><<<dim3(8, 8), 224, SCAN_SMEM_LR>>>(w_rl, 99,   99,   98,   -1, 100);

    head_kernel<<<(NPIX + 255) / 256, 256>>>(w2, b2);
    upsample_kernel<<<(SEG_ELEMS + 255) / 256, 256>>>(out);
    pool_kernel<<<(NB * 900 + 255) / 256, 256>>>();
    fc1_kernel<<<NB, 128>>>(fc1w, fc1b);
    fc2_kernel<<<1, 32>>>(fc2w, fc2b, out + SEG_ELEMS);
}

// round 10
// speedup vs baseline: 1.0814x; 1.0527x over previous
#include <cuda_runtime.h>
#include <math.h>

#define NB   8
#define HH   36
#define WW   100
#define HW   3600
#define C0   512
#define C1   1024
#define C2   128
#define NCLS 5
#define NPIX 28800
#define K1   4608
#define SEG_ELEMS 9216000

__device__ __align__(16) float g_h1[NB * C1 * HW];
__device__ __align__(16) float g_h2[NB * C2 * HW];
__device__ __align__(16) float g_score[NB * NCLS * HW];
__device__ __align__(16) float g_pool[NB * 4500];
__device__ __align__(16) float g_f1[NB * 128];
__device__ unsigned g_bar_count[NB];
__device__ unsigned g_bar_gen[NB];

// =====================================================================
// conv1: dilated 3x3 (dil=4,pad=4) 512->1024 + BN + ReLU.
// GEMM M=1024, N=28800, K=4608. 128x128x8 tiles, double-buffered.
// B gather vectorized: 4-pixel groups share a row; +/-4 dilation keeps the
// float4 window fully in- or out-of-bounds -> one predicated LDG.128.
// =====================================================================
__global__ __launch_bounds__(256, 2)
void conv1_kernel(const float* __restrict__ x, const float* __restrict__ w,
                  const float* __restrict__ bg, const float* __restrict__ bb,
                  const float* __restrict__ bm, const float* __restrict__ bv)
{
    __shared__ float As[2][8][128];
    __shared__ float Bs[2][8][128];
    const int n0 = blockIdx.x * 128;
    const int m0 = blockIdx.y * 128;
    const int t  = threadIdx.x;
    const int tx = t & 15, ty = t >> 4;

    // B-load mapping: k-row bk, 4-pixel group at bn4
    const int bk  = t >> 5;
    const int bn4 = (t & 31) << 2;
    const int p0  = n0 + bn4;            // aligned 4; group within one image row
    const int pB  = p0 / HW;
    const int rrem = p0 - pB * HW;
    const int oh  = rrem / WW;
    const int w0  = rrem - oh * WW;      // multiple of 4
    const float* xplane = x + (size_t)pB * C0 * HW;

    const int aRow = t >> 1;
    const int aCol = (t & 1) << 2;
    const float* aPtr = w + (size_t)(m0 + aRow) * K1 + aCol;

    int ci = 0, kk = bk;   // incremental (ci, kk) for k = k0 + bk

    float acc[8][8];
#pragma unroll
    for (int i = 0; i < 8; i++)
#pragma unroll
        for (int j = 0; j < 8; j++) acc[i][j] = 0.f;

    // prologue
    {
        float4 av = __ldg((const float4*)aPtr);
        As[0][aCol + 0][aRow] = av.x;
        As[0][aCol + 1][aRow] = av.y;
        As[0][aCol + 2][aRow] = av.z;
        As[0][aCol + 3][aRow] = av.w;
        int kh = kk / 3, kwv = kk - kh * 3;
        int ih = oh + kh * 4 - 4, iw0 = w0 + kwv * 4 - 4;
        float4 v = make_float4(0.f, 0.f, 0.f, 0.f);
        if ((unsigned)ih < (unsigned)HH && (unsigned)iw0 <= (unsigned)(WW - 4))
            v = *(const float4*)(xplane + ((size_t)ci * HH + ih) * WW + iw0);
        *(float4*)&Bs[0][bk][bn4] = v;
    }
    __syncthreads();

    int buf = 0;
    for (int k0 = 0; k0 < K1; k0 += 8) {
        float4 avN, bvN;
        const bool more = (k0 + 8) < K1;
        if (more) {
            avN = __ldg((const float4*)(aPtr + k0 + 8));
            if (kk == 0) kk = 8; else { kk -= 1; ci += 1; }
            int kh = kk / 3, kwv = kk - kh * 3;
            int ih = oh + kh * 4 - 4, iw0 = w0 + kwv * 4 - 4;
            bvN = make_float4(0.f, 0.f, 0.f, 0.f);
            if ((unsigned)ih < (unsigned)HH && (unsigned)iw0 <= (unsigned)(WW - 4))
                bvN = *(const float4*)(xplane + ((size_t)ci * HH + ih) * WW + iw0);
        }

#pragma unroll
        for (int kk2 = 0; kk2 < 8; kk2++) {
            float ar[8], br[8];
#pragma unroll
            for (int i = 0; i < 8; i++) ar[i] = As[buf][kk2][ty * 8 + i];
#pragma unroll
            for (int j = 0; j < 8; j++) br[j] = Bs[buf][kk2][tx * 8 + j];
#pragma unroll
            for (int i = 0; i < 8; i++)
#pragma unroll
                for (int j = 0; j < 8; j++) acc[i][j] += ar[i] * br[j];
        }

        if (more) {
            int nb = buf ^ 1;
            As[nb][aCol + 0][aRow] = avN.x;
            As[nb][aCol + 1][aRow] = avN.y;
            As[nb][aCol + 2][aRow] = avN.z;
            As[nb][aCol + 3][aRow] = avN.w;
            *(float4*)&Bs[nb][bk][bn4] = bvN;
        }
        __syncthreads();
        buf ^= 1;
    }

#pragma unroll
    for (int i = 0; i < 8; i++) {
        int co = m0 + ty * 8 + i;
        float s    = bg[co] / sqrtf(bv[co] + 1e-5f);
        float bias = bb[co] - bm[co] * s;
#pragma unroll
        for (int j = 0; j < 8; j++) {
            int n  = n0 + tx * 8 + j;
            int b_ = n / HW;
            int r  = n - b_ * HW;
            float v = acc[i][j] * s + bias;
            g_h1[(size_t)(b_ * C1 + co) * HW + r] = fmaxf(v, 0.f);
        }
    }
}

// =====================================================================
// conv2: 1x1 1024->128 + BN + ReLU. GEMM M=128, N=28800, K=1024.
// B loads vectorized (contiguous within channel plane).
// =====================================================================
__global__ __launch_bounds__(256)
void conv2_kernel(const float* __restrict__ w,
                  const float* __restrict__ bg, const float* __restrict__ bb,
                  const float* __restrict__ bm, const float* __restrict__ bv)
{
    __shared__ float As[8][128];
    __shared__ float Bs[8][128];
    const int n0 = blockIdx.x * 128;
    const int t  = threadIdx.x;
    const int tx = t & 15, ty = t >> 4;

    const int bk  = t >> 5;
    const int bn4 = (t & 31) << 2;
    const int p0  = n0 + bn4;
    const int pB  = p0 / HW;
    const int pr0 = p0 - pB * HW;
    const float* hplane = g_h1 + (size_t)pB * C1 * HW + pr0;

    const int aRow = t >> 1;
    const int aCol = (t & 1) << 2;
    const float* aPtr = w + (size_t)aRow * C1 + aCol;

    float acc[8][8];
#pragma unroll
    for (int i = 0; i < 8; i++)
#pragma unroll
        for (int j = 0; j < 8; j++) acc[i][j] = 0.f;

    for (int k0 = 0; k0 < C1; k0 += 8) {
        float4 av = *(const float4*)(aPtr + k0);
        As[aCol + 0][aRow] = av.x;
        As[aCol + 1][aRow] = av.y;
        As[aCol + 2][aRow] = av.z;
        As[aCol + 3][aRow] = av.w;

        int k = k0 + bk;
        *(float4*)&Bs[bk][bn4] = *(const float4*)(hplane + (size_t)k * HW);
        __syncthreads();

#pragma unroll
        for (int kk2 = 0; kk2 < 8; kk2++) {
            float ar[8], br[8];
#pragma unroll
            for (int i = 0; i < 8; i++) ar[i] = As[kk2][ty * 8 + i];
#pragma unroll
            for (int j = 0; j < 8; j++) br[j] = Bs[kk2][tx * 8 + j];
#pragma unroll
            for (int i = 0; i < 8; i++)
#pragma unroll
                for (int j = 0; j < 8; j++) acc[i][j] += ar[i] * br[j];
        }
        __syncthreads();
    }

#pragma unroll
    for (int i = 0; i < 8; i++) {
        int co = ty * 8 + i;
        float s    = bg[co] / sqrtf(bv[co] + 1e-5f);
        float bias = bb[co] - bm[co] * s;
#pragma unroll
        for (int j = 0; j < 8; j++) {
            int n  = n0 + tx * 8 + j;
            int b_ = n / HW;
            int r  = n - b_ * HW;
            float v = acc[i][j] * s + bias;
            g_h2[(size_t)(b_ * C2 + co) * HW + r] = fmaxf(v, 0.f);
        }
    }
}

// =====================================================================
// persistent scan kernels (unchanged)
// =====================================================================
__device__ __forceinline__ void batch_barrier(int b, unsigned nb)
{
    __syncthreads();
    if (threadIdx.x == 0) {
        __threadfence();
        volatile unsigned* genp = &g_bar_gen[b];
        unsigned my = *genp;
        unsigned a  = atomicAdd(&g_bar_count[b], 1u);
        if (a == nb - 1u) {
            atomicExch(&g_bar_count[b], 0u);
            __threadfence();
            *genp = my + 1u;
        } else {
            while (*genp == my) { __nanosleep(64); }
        }
        __threadfence();
    }
    __syncthreads();
}

template <int L, int COB, int NBLK>
__global__ __launch_bounds__(224, 1)
void scan_kernel(const float* __restrict__ wgt, int nSteps,
                 int prevOff0, int curOff0, int dOff, int posStride)
{
    constexpr int THREADS = 224;
    constexpr int LP = L + 8;
    extern __shared__ float sm[];
    float* prev = sm;
    float* ws   = sm + 128 * LP;

    const int b   = blockIdx.x;
    const int cog = blockIdx.y * COB;
    const int tid = threadIdx.x;

    for (int i = tid; i < COB * 128 * 9; i += THREADS)
        ws[i] = __ldg(wgt + (size_t)cog * 128 * 9 + i);

    constexpr int NSEG = L / 4;
    constexpr int NT   = COB * NSEG;
    const int co = tid / NSEG;
    const int p0 = (tid - co * NSEG) * 4;

    int prevOff = prevOff0, curOff = curOff0;
    for (int s = 0; s < nSteps; s++) {
        if (s) batch_barrier(b, NBLK);
        else   __syncthreads();

        for (int i = tid; i < 128 * LP; i += THREADS) {
            int ci = i / LP;
            int p  = i - ci * LP - 4;
            float v = 0.f;
            if ((unsigned)p < (unsigned)L)
                v = __ldcg(&g_h2[(size_t)(b * C2 + ci) * HW + prevOff + p * posStride]);
            prev[i] = v;
        }
        __syncthreads();

        if (tid < NT) {
            float acc0 = 0.f, acc1 = 0.f, acc2 = 0.f, acc3 = 0.f;
            const float* wbase = ws + (size_t)co * 128 * 9;
            for (int ci = 0; ci < 128; ci++) {
                const float4* pr4 = (const float4*)(prev + ci * LP + p0);
                float4 a0 = pr4[0], a1 = pr4[1], a2 = pr4[2];
                float xv[12] = {a0.x, a0.y, a0.z, a0.w,
                                a1.x, a1.y, a1.z, a1.w,
                                a2.x, a2.y, a2.z, a2.w};
                const float* wp = wbase + ci * 9;
#pragma unroll
                for (int k = 0; k < 9; k++) {
                    float wk = wp[k];
                    acc0 += xv[k]     * wk;
                    acc1 += xv[k + 1] * wk;
                    acc2 += xv[k + 2] * wk;
                    acc3 += xv[k + 3] * wk;
                }
            }
            const size_t base = (size_t)(b * C2 + cog + co) * HW + curOff;
            float* o0 = &g_h2[base + (size_t)(p0 + 0) * posStride];
            float* o1 = &g_h2[base + (size_t)(p0 + 1) * posStride];
            float* o2 = &g_h2[base + (size_t)(p0 + 2) * posStride];
            float* o3 = &g_h2[base + (size_t)(p0 + 3) * posStride];
            *o0 = __ldcg(o0) + fmaxf(acc0, 0.f);
            *o1 = __ldcg(o1) + fmaxf(acc1, 0.f);
            *o2 = __ldcg(o2) + fmaxf(acc2, 0.f);
            *o3 = __ldcg(o3) + fmaxf(acc3, 0.f);
        }
        prevOff += dOff;
        curOff  += dOff;
    }
}

#define SCAN_SMEM_UD ((128 * 108 + 8  * 128 * 9) * 4)
#define SCAN_SMEM_LR ((128 * 44  + 16 * 128 * 9) * 4)

// =====================================================================
// tail kernels (unchanged)
// =====================================================================
__global__ void head_kernel(const float* __restrict__ w2, const float* __restrict__ b2)
{
    int n = blockIdx.x * blockDim.x + threadIdx.x;
    if (n >= NPIX) return;
    int b = n / HW;
    int r = n - b * HW;
    float s[NCLS];
#pragma unroll
    for (int c = 0; c < NCLS; c++) s[c] = b2[c];
    const float* hp = g_h2 + (size_t)b * C2 * HW + r;
    for (int ci = 0; ci < C2; ci++) {
        float v = hp[(size_t)ci * HW];
#pragma unroll
        for (int c = 0; c < NCLS; c++) s[c] += v * __ldg(w2 + c * C2 + ci);
    }
#pragma unroll
    for (int c = 0; c < NCLS; c++)
        g_score[(size_t)(b * NCLS + c) * HW + r] = s[c];
}

__global__ void upsample_kernel(float* __restrict__ out)
{
    int idx = blockIdx.x * blockDim.x + threadIdx.x;
    if (idx >= SEG_ELEMS) return;
    int ow = idx % 800;
    int t  = idx / 800;
    int oh = t % 288;
    int plane = t / 288;

    const float SHs = (float)(35.0 / 287.0);
    const float SWs = (float)(99.0 / 799.0);
    float ph = (float)oh * SHs;
    int i0 = (int)ph; if (i0 > 34) i0 = 34;
    float fh = ph - (float)i0;
    float pw = (float)ow * SWs;
    int j0 = (int)pw; if (j0 > 98) j0 = 98;
    float fw = pw - (float)j0;

    const float* sp = g_score + (size_t)plane * HW + i0 * WW + j0;
    float v00 = sp[0], v01 = sp[1], v10 = sp[WW], v11 = sp[WW + 1];
    float c0 = v00 * (1.f - fh) + v10 * fh;
    float c1 = v01 * (1.f - fh) + v11 * fh;
    out[idx] = c0 * (1.f - fw) + c1 * fw;
}

__global__ void pool_kernel()
{
    int t = blockIdx.x * blockDim.x + threadIdx.x;
    if (t >= NB * 18 * 50) return;
    int w2_ = t % 50;
    int h2_ = (t / 50) % 18;
    int b   = t / 900;
    float ac[NCLS] = {0, 0, 0, 0, 0};
#pragma unroll
    for (int dy = 0; dy < 2; dy++)
#pragma unroll
        for (int dx = 0; dx < 2; dx++) {
            int r = (h2_ * 2 + dy) * WW + (w2_ * 2 + dx);
            float sc[NCLS];
            float mx = -1e30f;
#pragma unroll
            for (int c = 0; c < NCLS; c++) {
                sc[c] = g_score[(size_t)(b * NCLS + c) * HW + r];
                mx = fmaxf(mx, sc[c]);
            }
            float sum = 0.f;
#pragma unroll
            for (int c = 0; c < NCLS; c++) { sc[c] = expf(sc[c] - mx); sum += sc[c]; }
            float inv = 1.f / sum;
#pragma unroll
            for (int c = 0; c < NCLS; c++) ac[c] += sc[c] * inv;
        }
#pragma unroll
    for (int c = 0; c < NCLS; c++)
        g_pool[(size_t)b * 4500 + c * 900 + h2_ * 50 + w2_] = ac[c] * 0.25f;
}

__global__ __launch_bounds__(128)
void fc1_kernel(const float* __restrict__ w, const float* __restrict__ bias)
{
    __shared__ float sp[4500];
    int b = blockIdx.x, j = threadIdx.x;
    for (int i = j; i < 4500; i += 128) sp[i] = g_pool[(size_t)b * 4500 + i];
    __syncthreads();
    float acc = bias[j];
    const float* wr = w + (size_t)j * 4500;
    for (int i = 0; i < 4500; i += 4) {
        float4 wv = *(const float4*)(wr + i);
        acc += wv.x * sp[i] + wv.y * sp[i + 1] + wv.z * sp[i + 2] + wv.w * sp[i + 3];
    }
    g_f1[b * 128 + j] = fmaxf(acc, 0.f);
}

__global__ void fc2_kernel(const float* __restrict__ w, const float* __restrict__ bias,
                           float* __restrict__ out)
{
    int t = threadIdx.x;
    if (t >= 32) return;
    int b = t >> 2, o = t & 3;
    float acc = bias[o];
    const float* wr = w + o * 128;
    const float* f  = g_f1 + b * 128;
    for (int i = 0; i < 128; i++) acc += wr[i] * f[i];
    out[b * 4 + o] = 1.f / (1.f + expf(-acc));
}

// =====================================================================
// launch
// =====================================================================
extern "C" void kernel_launch(void* const* d_in, const int* in_sizes, int n_in,
                              void* d_out, int out_size)
{
    const float* x    = (const float*)d_in[0];
    const float* w1a  = (const float*)d_in[1];
    const float* bn1g = (const float*)d_in[2];
    const float* bn1b = (const float*)d_in[3];
    const float* bn1m = (const float*)d_in[4];
    const float* bn1v = (const float*)d_in[5];
    const float* w1b  = (const float*)d_in[6];
    const float* bn2g = (const float*)d_in[7];
    const float* bn2b = (const float*)d_in[8];
    const float* bn2m = (const float*)d_in[9];
    const float* bn2v = (const float*)d_in[10];
    const float* w_ud = (const float*)d_in[11];
    const float* w_du = (const float*)d_in[12];
    const float* w_lr = (const float*)d_in[13];
    const float* w_rl = (const float*)d_in[14];
    const float* w2   = (const float*)d_in[15];
    const float* b2   = (const float*)d_in[16];
    const float* fc1w = (const float*)d_in[17];
    const float* fc1b = (const float*)d_in[18];
    const float* fc2w = (const float*)d_in[19];
    const float* fc2b = (const float*)d_in[20];
    float* out = (float*)d_out;

    cudaFuncSetAttribute(scan_kernel<100, 8, 16>,
                         cudaFuncAttributeMaxDynamicSharedMemorySize, SCAN_SMEM_UD);
    cudaFuncSetAttribute(scan_kernel<36, 16, 8>,
                         cudaFuncAttributeMaxDynamicSharedMemorySize, SCAN_SMEM_LR);

    conv1_kernel<<<dim3(225, 8), 256>>>(x, w1a, bn1g, bn1b, bn1m, bn1v);
    conv2_kernel<<<dim3(225, 1), 256>>>(w1b, bn2g, bn2b, bn2m, bn2v);

    scan_kernel<100, 8, 16><<<dim3(8, 16), 224, SCAN_SMEM_UD>>>(w_ud, 35,    0,  100,  100, 1);
    scan_kernel<100, 8, 16><<<dim3(8, 16), 224, SCAN_SMEM_UD>>>(w_du, 35, 3500, 3400, -100, 1);
    scan_kernel<36, 16, 8><<<dim3(8, 8), 224, SCAN_SMEM_LR>>>(w_lr, 99,    0,    1,    1, 100);
    scan_kernel<36, 16, 8><<<dim3(8, 8), 224, SCAN_SMEM_LR>>>(w_rl, 99,   99,   98,   -1, 100);

    head_kernel<<<(NPIX + 255) / 256, 256>>>(w2, b2);
    upsample_kernel<<<(SEG_ELEMS + 255) / 256, 256>>>(out);
    pool_kernel<<<(NB * 900 + 255) / 256, 256>>>();
    fc1_kernel<<<NB, 128>>>(fc1w, fc1b);
    fc2_kernel<<<1, 32>>>(fc2w, fc2b, out + SEG_ELEMS);
}

// round 16
// speedup vs baseline: 1.6663x; 1.5409x over previous
#include <cuda_runtime.h>
#include <math.h>
#include <stdint.h>

#define NB   8
#define HH   36
#define WW   100
#define HW   3600
#define C0   512
#define C1   1024
#define C2   128
#define NCLS 5
#define NPIX 28800
#define K1   4608
#define SEG_ELEMS 9216000

__device__ __align__(16) float g_h1[NB * C1 * HW];
__device__ __align__(16) float g_h2[NB * C2 * HW];
__device__ __align__(16) float g_score[NB * NCLS * HW];
__device__ __align__(16) float g_pool[NB * 4500];
__device__ __align__(16) float g_f1[NB * 128];
__device__ unsigned g_bar_count[NB];
__device__ unsigned g_bar_gen[NB];

// ---------------- tf32 mma.sync helpers (portable PTX, sm_80+) ----------------
__device__ __forceinline__ float tf32r(float x) {
    uint32_t u;
    asm("cvt.rna.tf32.f32 %0, %1;" : "=r"(u) : "f"(x));
    return __uint_as_float(u);
}
__device__ __forceinline__ void mma_tf32(float* d, const uint32_t* a, const uint32_t* b) {
    asm volatile(
        "mma.sync.aligned.m16n8k8.row.col.f32.tf32.tf32.f32 "
        "{%0,%1,%2,%3}, {%4,%5,%6,%7}, {%8,%9}, {%0,%1,%2,%3};"
        : "+f"(d[0]), "+f"(d[1]), "+f"(d[2]), "+f"(d[3])
        : "r"(a[0]), "r"(a[1]), "r"(a[2]), "r"(a[3]), "r"(b[0]), "r"(b[1]));
}

// =====================================================================
// conv1 via tf32 mma.sync: dilated 3x3 (dil=4,pad=4) 512->1024 + BN + ReLU.
// GEMM M=1024, N=28800, K=4608. CTA tile 128x128, K-chunk 8, double-buffered.
// 8 warps = 2(M) x 4(N); warp tile 64x32 = 4x4 m16n8k8 fragments.
// smem rows padded to 136 floats -> conflict-free fragment LDS.
// =====================================================================
#define SPAD 136

__global__ __launch_bounds__(256, 2)
void conv1_tc_kernel(const float* __restrict__ x, const float* __restrict__ w,
                     const float* __restrict__ bg, const float* __restrict__ bb,
                     const float* __restrict__ bm, const float* __restrict__ bv)
{
    __shared__ float As[2][8][SPAD];   // [k][m], tf32-rounded
    __shared__ float Bs[2][8][SPAD];   // [k][n], tf32-rounded
    const int n0 = blockIdx.x * 128;
    const int m0 = blockIdx.y * 128;
    const int t  = threadIdx.x;
    const int wid  = t >> 5;
    const int lane = t & 31;
    const int gid  = lane >> 2;   // groupID 0..7
    const int tig  = lane & 3;    // thread-in-group 0..3
    const int warpM = (wid >> 2) * 64;  // 0 or 64
    const int warpN = (wid & 3) * 32;   // 0..96

    // ---- global load mappings (same as proven R10 kernel) ----
    // B loader: k-row bk, 4-pixel group bn4
    const int bk  = t >> 5;
    const int bn4 = (t & 31) << 2;
    const int p0  = n0 + bn4;
    const int pB  = p0 / HW;
    const int rrem = p0 - pB * HW;
    const int oh  = rrem / WW;
    const int w0  = rrem - oh * WW;    // multiple of 4
    const float* xplane = x + (size_t)pB * C0 * HW;
    // A loader: row aRow (m), k-quad aCol
    const int aRow = t >> 1;
    const int aCol = (t & 1) << 2;
    const float* aPtr = w + (size_t)(m0 + aRow) * K1 + aCol;

    int ci = 0, kk = bk;   // incremental (ci,kk) for k = k0 + bk

    float acc[4][4][4];
#pragma unroll
    for (int i = 0; i < 4; i++)
#pragma unroll
        for (int j = 0; j < 4; j++)
#pragma unroll
            for (int q = 0; q < 4; q++) acc[i][j][q] = 0.f;

    // prologue: fill buffer 0
    {
        float4 av = __ldg((const float4*)aPtr);
        As[0][aCol + 0][aRow] = tf32r(av.x);
        As[0][aCol + 1][aRow] = tf32r(av.y);
        As[0][aCol + 2][aRow] = tf32r(av.z);
        As[0][aCol + 3][aRow] = tf32r(av.w);
        int kh = kk / 3, kwv = kk - kh * 3;
        int ih = oh + kh * 4 - 4, iw0 = w0 + kwv * 4 - 4;
        float4 v = make_float4(0.f, 0.f, 0.f, 0.f);
        if ((unsigned)ih < (unsigned)HH && (unsigned)iw0 <= (unsigned)(WW - 4))
            v = *(const float4*)(xplane + ((size_t)ci * HH + ih) * WW + iw0);
        float* bd = &Bs[0][bk][bn4];
        bd[0] = tf32r(v.x); bd[1] = tf32r(v.y); bd[2] = tf32r(v.z); bd[3] = tf32r(v.w);
    }
    __syncthreads();

    int buf = 0;
    for (int k0 = 0; k0 < K1; k0 += 8) {
        float4 avN, bvN;
        const bool more = (k0 + 8) < K1;
        if (more) {
            avN = __ldg((const float4*)(aPtr + k0 + 8));
            if (kk == 0) kk = 8; else { kk -= 1; ci += 1; }
            int kh = kk / 3, kwv = kk - kh * 3;
            int ih = oh + kh * 4 - 4, iw0 = w0 + kwv * 4 - 4;
            bvN = make_float4(0.f, 0.f, 0.f, 0.f);
            if ((unsigned)ih < (unsigned)HH && (unsigned)iw0 <= (unsigned)(WW - 4))
                bvN = *(const float4*)(xplane + ((size_t)ci * HH + ih) * WW + iw0);
        }

        // ---- tensor-core compute on current buffer ----
        {
            uint32_t afr[4][4], bfr[4][2];
            const float* A0 = &As[buf][0][0];
            const float* B0 = &Bs[buf][0][0];
#pragma unroll
            for (int mt = 0; mt < 4; mt++) {
                int m = warpM + mt * 16 + gid;
                afr[mt][0] = __float_as_uint(A0[tig * SPAD + m]);
                afr[mt][1] = __float_as_uint(A0[tig * SPAD + m + 8]);
                afr[mt][2] = __float_as_uint(A0[(tig + 4) * SPAD + m]);
                afr[mt][3] = __float_as_uint(A0[(tig + 4) * SPAD + m + 8]);
            }
#pragma unroll
            for (int nt = 0; nt < 4; nt++) {
                int n = warpN + nt * 8 + gid;
                bfr[nt][0] = __float_as_uint(B0[tig * SPAD + n]);
                bfr[nt][1] = __float_as_uint(B0[(tig + 4) * SPAD + n]);
            }
#pragma unroll
            for (int mt = 0; mt < 4; mt++)
#pragma unroll
                for (int nt = 0; nt < 4; nt++)
                    mma_tf32(acc[mt][nt], afr[mt], bfr[nt]);
        }

        if (more) {
            int nb = buf ^ 1;
            As[nb][aCol + 0][aRow] = tf32r(avN.x);
            As[nb][aCol + 1][aRow] = tf32r(avN.y);
            As[nb][aCol + 2][aRow] = tf32r(avN.z);
            As[nb][aCol + 3][aRow] = tf32r(avN.w);
            float* bd = &Bs[nb][bk][bn4];
            bd[0] = tf32r(bvN.x); bd[1] = tf32r(bvN.y); bd[2] = tf32r(bvN.z); bd[3] = tf32r(bvN.w);
        }
        __syncthreads();
        buf ^= 1;
    }

    // ---- epilogue: BN + ReLU, scatter to g_h1 ----
#pragma unroll
    for (int mt = 0; mt < 4; mt++) {
        int r0 = m0 + warpM + mt * 16 + gid;
        int r1 = r0 + 8;
        float s0 = bg[r0] / sqrtf(bv[r0] + 1e-5f);
        float bi0 = bb[r0] - bm[r0] * s0;
        float s1 = bg[r1] / sqrtf(bv[r1] + 1e-5f);
        float bi1 = bb[r1] - bm[r1] * s1;
#pragma unroll
        for (int nt = 0; nt < 4; nt++) {
            int c0 = n0 + warpN + nt * 8 + 2 * tig;
#pragma unroll
            for (int e = 0; e < 2; e++) {
                int np = c0 + e;
                int b_ = np / HW;
                int rr = np - b_ * HW;
                float v0 = acc[mt][nt][e]     * s0 + bi0;
                float v1 = acc[mt][nt][2 + e] * s1 + bi1;
                g_h1[((size_t)b_ * C1 + r0) * HW + rr] = fmaxf(v0, 0.f);
                g_h1[((size_t)b_ * C1 + r1) * HW + rr] = fmaxf(v1, 0.f);
            }
        }
    }
}

// =====================================================================
// conv2: 1x1 1024->128 + BN + ReLU (scalar SIMT, unchanged)
// =====================================================================
__global__ __launch_bounds__(256)
void conv2_kernel(const float* __restrict__ w,
                  const float* __restrict__ bg, const float* __restrict__ bb,
                  const float* __restrict__ bm, const float* __restrict__ bv)
{
    __shared__ float As[8][128];
    __shared__ float Bs[8][128];
    const int n0 = blockIdx.x * 128;
    const int t  = threadIdx.x;
    const int tx = t & 15, ty = t >> 4;

    const int bk  = t >> 5;
    const int bn4 = (t & 31) << 2;
    const int p0  = n0 + bn4;
    const int pB  = p0 / HW;
    const int pr0 = p0 - pB * HW;
    const float* hplane = g_h1 + (size_t)pB * C1 * HW + pr0;

    const int aRow = t >> 1;
    const int aCol = (t & 1) << 2;
    const float* aPtr = w + (size_t)aRow * C1 + aCol;

    float acc[8][8];
#pragma unroll
    for (int i = 0; i < 8; i++)
#pragma unroll
        for (int j = 0; j < 8; j++) acc[i][j] = 0.f;

    for (int k0 = 0; k0 < C1; k0 += 8) {
        float4 av = *(const float4*)(aPtr + k0);
        As[aCol + 0][aRow] = av.x;
        As[aCol + 1][aRow] = av.y;
        As[aCol + 2][aRow] = av.z;
        As[aCol + 3][aRow] = av.w;
        int k = k0 + bk;
        *(float4*)&Bs[bk][bn4] = *(const float4*)(hplane + (size_t)k * HW);
        __syncthreads();
#pragma unroll
        for (int kk2 = 0; kk2 < 8; kk2++) {
            float ar[8], br[8];
#pragma unroll
            for (int i = 0; i < 8; i++) ar[i] = As[kk2][ty * 8 + i];
#pragma unroll
            for (int j = 0; j < 8; j++) br[j] = Bs[kk2][tx * 8 + j];
#pragma unroll
            for (int i = 0; i < 8; i++)
#pragma unroll
                for (int j = 0; j < 8; j++) acc[i][j] += ar[i] * br[j];
        }
        __syncthreads();
    }

#pragma unroll
    for (int i = 0; i < 8; i++) {
        int co = ty * 8 + i;
        float s    = bg[co] / sqrtf(bv[co] + 1e-5f);
        float bias = bb[co] - bm[co] * s;
#pragma unroll
        for (int j = 0; j < 8; j++) {
            int n  = n0 + tx * 8 + j;
            int b_ = n / HW;
            int r  = n - b_ * HW;
            float v = acc[i][j] * s + bias;
            g_h2[(size_t)(b_ * C2 + co) * HW + r] = fmaxf(v, 0.f);
        }
    }
}

// =====================================================================
// persistent scan kernels (unchanged)
// =====================================================================
__device__ __forceinline__ void batch_barrier(int b, unsigned nb)
{
    __syncthreads();
    if (threadIdx.x == 0) {
        __threadfence();
        volatile unsigned* genp = &g_bar_gen[b];
        unsigned my = *genp;
        unsigned a  = atomicAdd(&g_bar_count[b], 1u);
        if (a == nb - 1u) {
            atomicExch(&g_bar_count[b], 0u);
            __threadfence();
            *genp = my + 1u;
        } else {
            while (*genp == my) { __nanosleep(64); }
        }
        __threadfence();
    }
    __syncthreads();
}

template <int L, int COB, int NBLK>
__global__ __launch_bounds__(224, 1)
void scan_kernel(const float* __restrict__ wgt, int nSteps,
                 int prevOff0, int curOff0, int dOff, int posStride)
{
    constexpr int THREADS = 224;
    constexpr int LP = L + 8;
    extern __shared__ float sm[];
    float* prev = sm;
    float* ws   = sm + 128 * LP;

    const int b   = blockIdx.x;
    const int cog = blockIdx.y * COB;
    const int tid = threadIdx.x;

    for (int i = tid; i < COB * 128 * 9; i += THREADS)
        ws[i] = __ldg(wgt + (size_t)cog * 128 * 9 + i);

    constexpr int NSEG = L / 4;
    constexpr int NT   = COB * NSEG;
    const int co = tid / NSEG;
    const int p0 = (tid - co * NSEG) * 4;

    int prevOff = prevOff0, curOff = curOff0;
    for (int s = 0; s < nSteps; s++) {
        if (s) batch_barrier(b, NBLK);
        else   __syncthreads();

        for (int i = tid; i < 128 * LP; i += THREADS) {
            int ci = i / LP;
            int p  = i - ci * LP - 4;
            float v = 0.f;
            if ((unsigned)p < (unsigned)L)
                v = __ldcg(&g_h2[(size_t)(b * C2 + ci) * HW + prevOff + p * posStride]);
            prev[i] = v;
        }
        __syncthreads();

        if (tid < NT) {
            float acc0 = 0.f, acc1 = 0.f, acc2 = 0.f, acc3 = 0.f;
            const float* wb = ws + (size_t)co * 128 * 9;
            for (int ci = 0; ci < 128; ci++) {
                const float4* pr4 = (const float4*)(prev + ci * LP + p0);
                float4 a0 = pr4[0], a1 = pr4[1], a2 = pr4[2];
                float xv[12] = {a0.x, a0.y, a0.z, a0.w,
                                a1.x, a1.y, a1.z, a1.w,
                                a2.x, a2.y, a2.z, a2.w};
                const float* wp = wb + ci * 9;
#pragma unroll
                for (int k = 0; k < 9; k++) {
                    float wk = wp[k];
                    acc0 += xv[k]     * wk;
                    acc1 += xv[k + 1] * wk;
                    acc2 += xv[k + 2] * wk;
                    acc3 += xv[k + 3] * wk;
                }
            }
            const size_t base = (size_t)(b * C2 + cog + co) * HW + curOff;
            float* o0 = &g_h2[base + (size_t)(p0 + 0) * posStride];
            float* o1 = &g_h2[base + (size_t)(p0 + 1) * posStride];
            float* o2 = &g_h2[base + (size_t)(p0 + 2) * posStride];
            float* o3 = &g_h2[base + (size_t)(p0 + 3) * posStride];
            *o0 = __ldcg(o0) + fmaxf(acc0, 0.f);
            *o1 = __ldcg(o1) + fmaxf(acc1, 0.f);
            *o2 = __ldcg(o2) + fmaxf(acc2, 0.f);
            *o3 = __ldcg(o3) + fmaxf(acc3, 0.f);
        }
        prevOff += dOff;
        curOff  += dOff;
    }
}

#define SCAN_SMEM_UD ((128 * 108 + 8  * 128 * 9) * 4)
#define SCAN_SMEM_LR ((128 * 44  + 16 * 128 * 9) * 4)

// =====================================================================
// tail kernels (unchanged)
// =====================================================================
__global__ void head_kernel(const float* __restrict__ w2, const float* __restrict__ b2)
{
    int n = blockIdx.x * blockDim.x + threadIdx.x;
    if (n >= NPIX) return;
    int b = n / HW;
    int r = n - b * HW;
    float s[NCLS];
#pragma unroll
    for (int c = 0; c < NCLS; c++) s[c] = b2[c];
    const float* hp = g_h2 + (size_t)b * C2 * HW + r;
    for (int ci = 0; ci < C2; ci++) {
        float v = hp[(size_t)ci * HW];
#pragma unroll
        for (int c = 0; c < NCLS; c++) s[c] += v * __ldg(w2 + c * C2 + ci);
    }
#pragma unroll
    for (int c = 0; c < NCLS; c++)
        g_score[(size_t)(b * NCLS + c) * HW + r] = s[c];
}

__global__ void upsample_kernel(float* __restrict__ out)
{
    int idx = blockIdx.x * blockDim.x + threadIdx.x;
    if (idx >= SEG_ELEMS) return;
    int ow = idx % 800;
    int t  = idx / 800;
    int oh = t % 288;
    int plane = t / 288;

    const float SHs = (float)(35.0 / 287.0);
    const float SWs = (float)(99.0 / 799.0);
    float ph = (float)oh * SHs;
    int i0 = (int)ph; if (i0 > 34) i0 = 34;
    float fh = ph - (float)i0;
    float pw = (float)ow * SWs;
    int j0 = (int)pw; if (j0 > 98) j0 = 98;
    float fw = pw - (float)j0;

    const float* sp = g_score + (size_t)plane * HW + i0 * WW + j0;
    float v00 = sp[0], v01 = sp[1], v10 = sp[WW], v11 = sp[WW + 1];
    float c0 = v00 * (1.f - fh) + v10 * fh;
    float c1 = v01 * (1.f - fh) + v11 * fh;
    out[idx] = c0 * (1.f - fw) + c1 * fw;
}

__global__ void pool_kernel()
{
    int t = blockIdx.x * blockDim.x + threadIdx.x;
    if (t >= NB * 18 * 50) return;
    int w2_ = t % 50;
    int h2_ = (t / 50) % 18;
    int b   = t / 900;
    float ac[NCLS] = {0, 0, 0, 0, 0};
#pragma unroll
    for (int dy = 0; dy < 2; dy++)
#pragma unroll
        for (int dx = 0; dx < 2; dx++) {
            int r = (h2_ * 2 + dy) * WW + (w2_ * 2 + dx);
            float sc[NCLS];
            float mx = -1e30f;
#pragma unroll
            for (int c = 0; c < NCLS; c++) {
                sc[c] = g_score[(size_t)(b * NCLS + c) * HW + r];
                mx = fmaxf(mx, sc[c]);
            }
            float sum = 0.f;
#pragma unroll
            for (int c = 0; c < NCLS; c++) { sc[c] = expf(sc[c] - mx); sum += sc[c]; }
            float inv = 1.f / sum;
#pragma unroll
            for (int c = 0; c < NCLS; c++) ac[c] += sc[c] * inv;
        }
#pragma unroll
    for (int c = 0; c < NCLS; c++)
        g_pool[(size_t)b * 4500 + c * 900 + h2_ * 50 + w2_] = ac[c] * 0.25f;
}

__global__ __launch_bounds__(128)
void fc1_kernel(const float* __restrict__ w, const float* __restrict__ bias)
{
    __shared__ float sp[4500];
    int b = blockIdx.x, j = threadIdx.x;
    for (int i = j; i < 4500; i += 128) sp[i] = g_pool[(size_t)b * 4500 + i];
    __syncthreads();
    float acc = bias[j];
    const float* wr = w + (size_t)j * 4500;
    for (int i = 0; i < 4500; i += 4) {
        float4 wv = *(const float4*)(wr + i);
        acc += wv.x * sp[i] + wv.y * sp[i + 1] + wv.z * sp[i + 2] + wv.w * sp[i + 3];
    }
    g_f1[b * 128 + j] = fmaxf(acc, 0.f);
}

__global__ void fc2_kernel(const float* __restrict__ w, const float* __restrict__ bias,
                           float* __restrict__ out)
{
    int t = threadIdx.x;
    if (t >= 32) return;
    int b = t >> 2, o = t & 3;
    float acc = bias[o];
    const float* wr = w + o * 128;
    const float* f  = g_f1 + b * 128;
    for (int i = 0; i < 128; i++) acc += wr[i] * f[i];
    out[b * 4 + o] = 1.f / (1.f + expf(-acc));
}

// =====================================================================
// launch
// =====================================================================
extern "C" void kernel_launch(void* const* d_in, const int* in_sizes, int n_in,
                              void* d_out, int out_size)
{
    const float* x    = (const float*)d_in[0];
    const float* w1a  = (const float*)d_in[1];
    const float* bn1g = (const float*)d_in[2];
    const float* bn1b = (const float*)d_in[3];
    const float* bn1m = (const float*)d_in[4];
    const float* bn1v = (const float*)d_in[5];
    const float* w1b  = (const float*)d_in[6];
    const float* bn2g = (const float*)d_in[7];
    const float* bn2b = (const float*)d_in[8];
    const float* bn2m = (const float*)d_in[9];
    const float* bn2v = (const float*)d_in[10];
    const float* w_ud = (const float*)d_in[11];
    const float* w_du = (const float*)d_in[12];
    const float* w_lr = (const float*)d_in[13];
    const float* w_rl = (const float*)d_in[14];
    const float* w2   = (const float*)d_in[15];
    const float* b2   = (const float*)d_in[16];
    const float* fc1w = (const float*)d_in[17];
    const float* fc1b = (const float*)d_in[18];
    const float* fc2w = (const float*)d_in[19];
    const float* fc2b = (const float*)d_in[20];
    float* out = (float*)d_out;

    cudaFuncSetAttribute(scan_kernel<100, 8, 16>,
                         cudaFuncAttributeMaxDynamicSharedMemorySize, SCAN_SMEM_UD);
    cudaFuncSetAttribute(scan_kernel<36, 16, 8>,
                         cudaFuncAttributeMaxDynamicSharedMemorySize, SCAN_SMEM_LR);

    conv1_tc_kernel<<<dim3(225, 8), 256>>>(x, w1a, bn1g, bn1b, bn1m, bn1v);
    conv2_kernel<<<dim3(225, 1), 256>>>(w1b, bn2g, bn2b, bn2m, bn2v);

    scan_kernel<100, 8, 16><<<dim3(8, 16), 224, SCAN_SMEM_UD>>>(w_ud, 35,    0,  100,  100, 1);
    scan_kernel<100, 8, 16><<<dim3(8, 16), 224, SCAN_SMEM_UD>>>(w_du, 35, 3500, 3400, -100, 1);
    scan_kernel<36, 16, 8><<<dim3(8, 8), 224, SCAN_SMEM_LR>>>(w_lr, 99,    0,    1,    1, 100);
    scan_kernel<36, 16, 8><<<dim3(8, 8), 224, SCAN_SMEM_LR>>>(w_rl, 99,   99,   98,   -1, 100);

    head_kernel<<<(NPIX + 255) / 256, 256>>>(w2, b2);
    upsample_kernel<<<(SEG_ELEMS + 255) / 256, 256>>>(out);
    pool_kernel<<<(NB * 900 + 255) / 256, 256>>>();
    fc1_kernel<<<NB, 128>>>(fc1w, fc1b);
    fc2_kernel<<<1, 32>>>(fc2w, fc2b, out + SEG_ELEMS);
}